// round 4
// baseline (speedup 1.0000x reference)
#include <cuda_runtime.h>
#include <stdint.h>

#define N_NODES 10000
#define N_EDGES 160000
#define M_PAD   10112          // 79 * 128

// ---------------- device scratch (no allocations allowed) ----------------
__device__ float g_aggx [M_PAD * 256];     // Â X          (rows >= N zero)
__device__ float g_h1lo [M_PAD * 256];     // h1 cols 0..255
__device__ float g_h1hi [M_PAD * 256];     // h1 cols 256..511
__device__ float g_xw2  [N_NODES * 256];   // h1 @ W2
__device__ float g_w1t  [512 * 256];       // W1^T  [N=512][K=256]
__device__ float g_w2tlo[256 * 256];       // W2^T k<256   [N=256][K=256]
__device__ float g_w2thi[256 * 256];       // W2^T k>=256
__device__ unsigned g_mask1[160000];       // 5.12M dropout bits
__device__ unsigned g_mask2[80000];        // 2.56M dropout bits
__device__ float g_dinv[N_NODES];
__device__ int   g_cnt[N_NODES];
__device__ int   g_off[N_NODES + 1];
__device__ int   g_cur[N_NODES];
__device__ int   g_csr[N_EDGES];
__device__ int   g_is64 = 1;

// ---------------- PTX helpers (sm_90-baseline, OK on plain sm_103) -------
__device__ __forceinline__ uint32_t smem_to_u32(const void* p) {
    uint32_t a;
    asm("{ .reg .u64 t; cvta.to.shared.u64 t, %1; cvt.u32.u64 %0, t; }" : "=r"(a) : "l"(p));
    return a;
}
__device__ __forceinline__ uint32_t f2tf32(float f) {
    uint32_t r;
    asm("cvt.rna.tf32.f32 %0, %1;" : "=r"(r) : "f"(f));
    return r;
}
__device__ __forceinline__ void bulk_g2s(uint32_t dst, const void* src, uint32_t bytes, uint32_t mbar) {
    asm volatile("cp.async.bulk.shared::cluster.global.mbarrier::complete_tx::bytes [%0], [%1], %2, [%3];"
        :: "r"(dst), "l"(src), "r"(bytes), "r"(mbar) : "memory");
}
#define MBARRIER_INIT(mbar, count) \
    asm volatile("mbarrier.init.shared.b64 [%0], %1;" :: "r"(mbar), "r"((uint32_t)(count)) : "memory")
#define MBAR_EXPECT(mbar, bytes) \
    asm volatile("mbarrier.arrive.expect_tx.shared.b64 _, [%0], %1;" :: "r"(mbar), "r"((uint32_t)(bytes)) : "memory")
#define MBAR_WAIT(mbar_a, parity) do { \
    uint32_t _m = (mbar_a); uint32_t _p = (parity); uint32_t _done; \
    asm volatile("{\n\t.reg .pred p;\n\t" \
        "mbarrier.try_wait.parity.shared.b64 p, [%1], %2;\n\t" \
        "selp.b32 %0, 1, 0, p;\n\t}" : "=r"(_done) : "r"(_m), "r"(_p) : "memory"); \
    if (!_done) { \
        asm volatile("{\n\t.reg .pred P1;\n\t" \
            "WAIT_LOOP_%=:\n\t" \
            "mbarrier.try_wait.parity.shared.b64 P1, [%0], %1;\n\t" \
            "@P1 bra.uni WAIT_DONE_%=;\n\t" \
            "bra.uni WAIT_LOOP_%=;\n\t" \
            "WAIT_DONE_%=:\n\t}" :: "r"(_m), "r"(_p) : "memory"); \
    } \
} while (0)

// m16n8k8 tf32 MMA, row.col, fp32 accumulate
__device__ __forceinline__ void mma_tf32(float* d, const uint32_t* a, const uint32_t* b) {
    asm volatile(
        "mma.sync.aligned.m16n8k8.row.col.f32.tf32.tf32.f32 "
        "{%0,%1,%2,%3},{%4,%5,%6,%7},{%8,%9},{%0,%1,%2,%3};"
        : "+f"(d[0]), "+f"(d[1]), "+f"(d[2]), "+f"(d[3])
        : "r"(a[0]), "r"(a[1]), "r"(a[2]), "r"(a[3]), "r"(b[0]), "r"(b[1]));
}

// ---------------- threefry2x32 (JAX-compatible, validated R1/R3) ---------
#define TF_ROUND(v0, v1, r) do { (v0) += (v1); (v1) = ((v1) << (r)) | ((v1) >> (32 - (r))); (v1) ^= (v0); } while (0)
__host__ __device__ inline void tf2x32(unsigned k0, unsigned k1,
                                       unsigned x0, unsigned x1,
                                       unsigned& o0, unsigned& o1) {
    unsigned ks0 = k0, ks1 = k1, ks2 = k0 ^ k1 ^ 0x1BD11BDAu;
    unsigned v0 = x0 + ks0, v1 = x1 + ks1;
    TF_ROUND(v0, v1, 13); TF_ROUND(v0, v1, 15); TF_ROUND(v0, v1, 26); TF_ROUND(v0, v1, 6);
    v0 += ks1; v1 += ks2 + 1u;
    TF_ROUND(v0, v1, 17); TF_ROUND(v0, v1, 29); TF_ROUND(v0, v1, 16); TF_ROUND(v0, v1, 24);
    v0 += ks2; v1 += ks0 + 2u;
    TF_ROUND(v0, v1, 13); TF_ROUND(v0, v1, 15); TF_ROUND(v0, v1, 26); TF_ROUND(v0, v1, 6);
    v0 += ks0; v1 += ks1 + 3u;
    TF_ROUND(v0, v1, 17); TF_ROUND(v0, v1, 29); TF_ROUND(v0, v1, 16); TF_ROUND(v0, v1, 24);
    v0 += ks1; v1 += ks2 + 4u;
    TF_ROUND(v0, v1, 13); TF_ROUND(v0, v1, 15); TF_ROUND(v0, v1, 26); TF_ROUND(v0, v1, 6);
    v0 += ks2; v1 += ks0 + 5u;
    o0 = v0; o1 = v1;
}

// ---------------- preprocessing --------------------------------------------
__device__ inline int edge_at(const void* ei, int pos) {
    if (g_is64) return (int)((const long long*)ei)[pos];
    return ((const int*)ei)[pos];
}

__global__ void init_kernel(const int* __restrict__ ei32) {
    int t = blockIdx.x * blockDim.x + threadIdx.x;
    if (t < N_NODES) g_cnt[t] = 0;
    if (t < 1024) {
        // int64 edge data < 2^31 -> all odd 32-bit words zero
        if (ei32[t * 2 + 1] != 0) g_is64 = 0;
    }
}
__global__ void count_kernel(const void* __restrict__ ei) {
    int e = blockIdx.x * blockDim.x + threadIdx.x;
    if (e >= N_EDGES) return;
    atomicAdd(&g_cnt[edge_at(ei, N_EDGES + e)], 1);
}
__global__ void scan_kernel() {
    __shared__ int sh[1024];
    int carry = 0;
    for (int base = 0; base < N_NODES; base += 1024) {
        int i = base + (int)threadIdx.x;
        int v = (i < N_NODES) ? g_cnt[i] : 0;
        if (i < N_NODES) g_dinv[i] = rsqrtf((float)(v + 1));
        sh[threadIdx.x] = v;
        __syncthreads();
        for (int off = 1; off < 1024; off <<= 1) {
            int t = (threadIdx.x >= (unsigned)off) ? sh[threadIdx.x - off] : 0;
            __syncthreads();
            sh[threadIdx.x] += t;
            __syncthreads();
        }
        if (i < N_NODES) {
            int excl = sh[threadIdx.x] - v + carry;
            g_off[i] = excl;
            g_cur[i] = excl;
        }
        carry += sh[1023];
        __syncthreads();
    }
    if (threadIdx.x == 0) g_off[N_NODES] = carry;
}
__global__ void fill_kernel(const void* __restrict__ ei) {
    int e = blockIdx.x * blockDim.x + threadIdx.x;
    if (e >= N_EDGES) return;
    int s = edge_at(ei, e);
    int d = edge_at(ei, N_EDGES + e);
    g_csr[atomicAdd(&g_cur[d], 1)] = s;
}

// three transposes of [256, C] blocks, selected by blockIdx.z
__global__ void transpose3_kernel(const float* __restrict__ W1,
                                  const float* __restrict__ W2) {
    __shared__ float tile[32][33];
    int z = blockIdx.z;
    const float* src = (z == 0) ? W1 : (z == 1) ? W2 : (W2 + 256 * 256);
    float* dst = (z == 0) ? g_w1t : (z == 1) ? g_w2tlo : g_w2thi;
    int C = (z == 0) ? 512 : 256;     // src is [256, C], dst [C, 256]
    if (blockIdx.x * 32 >= C) return;
    int c0 = blockIdx.x * 32, r0 = blockIdx.y * 32;
#pragma unroll
    for (int i = 0; i < 32; i += 8) {
        int r = r0 + threadIdx.y + i, c = c0 + threadIdx.x;
        tile[threadIdx.y + i][threadIdx.x] = src[(size_t)r * C + c];
    }
    __syncthreads();
#pragma unroll
    for (int i = 0; i < 32; i += 8) {
        int c = c0 + threadIdx.y + i, r = r0 + threadIdx.x;
        dst[(size_t)c * 256 + r] = tile[threadIdx.x][threadIdx.y + i];
    }
}

// dropout bitmask: one thread per element, ballot to 32-bit words
__global__ void mask_kernel(unsigned* __restrict__ mask, unsigned k0, unsigned k1) {
    unsigned i = blockIdx.x * 256u + threadIdx.x;
    unsigned y0, y1;
    tf2x32(k0, k1, 0u, i, y0, y1);
    unsigned bits = y0 ^ y1;
    float u = __uint_as_float((bits >> 9) | 0x3f800000u) - 1.0f;
    unsigned ball = __ballot_sync(0xffffffffu, u < 0.5f);
    if ((threadIdx.x & 31) == 0) mask[i >> 5] = ball;
}

// ---------------- bulk-fed tf32 GEMM ---------------------------------------
// C[M, 256/512-wide group] = A[M,256] @ B[N,256]^T.
// Per CTA: A tile [128,256] resident (padded rows of 260 floats, bulk per row),
// B streamed in 64-row slices. NS slices per CTA; blockIdx.x = N-group.
// EPI: 0 = plain store, 1 = bias+relu+dropout, split to lo/hi, 2 = accumulate.
#define SROW 260
#define SROW_B 1040u

template <int NS, int EPI>
__global__ void __launch_bounds__(256) gemm_kernel(
    const float* __restrict__ A, const float* __restrict__ B,
    float* __restrict__ C0, float* __restrict__ C1,
    const float* __restrict__ bias, const unsigned* __restrict__ mask, int M)
{
    extern __shared__ float sm[];
    float* As = sm;                   // [128][260]
    float* Bs = sm + 128 * SROW;      // [64][260]
    __shared__ uint64_t mbar_s;
    const uint32_t mbar = smem_to_u32(&mbar_s);

    const int tid = threadIdx.x, wid = tid >> 5, lane = tid & 31;
    const int g = lane >> 2, tig = lane & 3;
    const int wm = wid >> 1, wn = wid & 1;
    const int bm = blockIdx.y * 128;
    const int gb = blockIdx.x * (NS * 64);

    if (tid == 0) MBARRIER_INIT(mbar, 1);
    __syncthreads();

    const uint32_t asb = smem_to_u32(As), bsb = smem_to_u32(Bs);
    if (tid == 0) {
        MBAR_EXPECT(mbar, 128 * 1024 + 64 * 1024);
        for (int r = 0; r < 128; r++)
            bulk_g2s(asb + r * SROW_B, A + (size_t)(bm + r) * 256, 1024, mbar);
        for (int r = 0; r < 64; r++)
            bulk_g2s(bsb + r * SROW_B, B + (size_t)(gb + r) * 256, 1024, mbar);
    }

    int cnum = 0;
    for (int ns = 0; ns < NS; ns++) {
        MBAR_WAIT(mbar, cnum & 1); cnum++;

        float acc[2][4][4];
#pragma unroll
        for (int mi = 0; mi < 2; mi++)
#pragma unroll
            for (int ni = 0; ni < 4; ni++)
#pragma unroll
                for (int j = 0; j < 4; j++) acc[mi][ni][j] = 0.0f;

        const int r0b = wm * 32;
        const int n0b = wn * 32;
#pragma unroll 4
        for (int s = 0; s < 32; s++) {
            int k0 = s * 8;
            uint32_t af[2][4];
#pragma unroll
            for (int mi = 0; mi < 2; mi++) {
                int r0 = r0b + mi * 16 + g;
                af[mi][0] = f2tf32(As[r0 * SROW + k0 + tig]);
                af[mi][1] = f2tf32(As[(r0 + 8) * SROW + k0 + tig]);
                af[mi][2] = f2tf32(As[r0 * SROW + k0 + tig + 4]);
                af[mi][3] = f2tf32(As[(r0 + 8) * SROW + k0 + tig + 4]);
            }
#pragma unroll
            for (int ni = 0; ni < 4; ni++) {
                int n0 = n0b + ni * 8 + g;
                uint32_t bf[2];
                bf[0] = f2tf32(Bs[n0 * SROW + k0 + tig]);
                bf[1] = f2tf32(Bs[n0 * SROW + k0 + tig + 4]);
                mma_tf32(acc[0][ni], af[0], bf);
                mma_tf32(acc[1][ni], af[1], bf);
            }
        }
        __syncthreads();           // all warps done reading Bs
        if (ns + 1 < NS && tid == 0) {
            MBAR_EXPECT(mbar, 64 * 1024);
            for (int r = 0; r < 64; r++)
                bulk_g2s(bsb + r * SROW_B, B + (size_t)(gb + (ns + 1) * 64 + r) * 256, 1024, mbar);
        }
        // epilogue (overlaps next B load)
#pragma unroll
        for (int mi = 0; mi < 2; mi++) {
#pragma unroll
            for (int h = 0; h < 2; h++) {
                int m = bm + wm * 32 + mi * 16 + g + h * 8;
                if (m >= M) continue;
#pragma unroll
                for (int ni = 0; ni < 4; ni++) {
                    int nloc = ns * 64 + wn * 32 + ni * 8 + tig * 2;
                    float v0 = acc[mi][ni][h * 2 + 0];
                    float v1 = acc[mi][ni][h * 2 + 1];
                    if (EPI == 0) {
                        int colg = blockIdx.x * (NS * 64) + nloc;
                        *(float2*)&C0[(size_t)m * 256 + colg] = make_float2(v0, v1);
                    } else if (EPI == 2) {
                        int colg = blockIdx.x * (NS * 64) + nloc;
                        float2 o = *(const float2*)&C0[(size_t)m * 256 + colg];
                        *(float2*)&C0[(size_t)m * 256 + colg] = make_float2(o.x + v0, o.y + v1);
                    } else {
                        int nglob = blockIdx.x * 256 + nloc;
                        float r0v = fmaxf(v0 + bias[nglob], 0.0f);
                        float r1v = fmaxf(v1 + bias[nglob + 1], 0.0f);
                        unsigned idx = (unsigned)m * 512u + (unsigned)nglob;
                        unsigned w = mask[idx >> 5];
                        r0v = ((w >> (idx & 31)) & 1u) ? r0v * 2.0f : 0.0f;
                        r1v = ((w >> ((idx + 1) & 31)) & 1u) ? r1v * 2.0f : 0.0f;
                        float* H = (blockIdx.x == 0) ? C0 : C1;
                        *(float2*)&H[(size_t)m * 256 + nloc] = make_float2(r0v, r1v);
                    }
                }
            }
        }
    }
}

// ---------------- aggregations ----------------------------------------------
__global__ void aggx_kernel(const float* __restrict__ x) {
    int n = blockIdx.x, c = threadIdx.x;
    float dn = g_dinv[n];
    float acc = dn * x[(size_t)n * 256 + c];
    int k0 = g_off[n], k1 = g_off[n + 1];
    for (int k = k0; k < k1; k++) {
        int s = g_csr[k];
        acc += g_dinv[s] * x[(size_t)s * 256 + c];
    }
    g_aggx[(size_t)n * 256 + c] = acc * dn;
}

__global__ void agg2_kernel(const float* __restrict__ xw,
                            const float* __restrict__ bias,
                            float* __restrict__ out) {
    int n = blockIdx.x, c = threadIdx.x;
    float dn = g_dinv[n];
    float acc = dn * xw[(size_t)n * 256 + c];
    int k0 = g_off[n], k1 = g_off[n + 1];
    for (int k = k0; k < k1; k++) {
        int s = g_csr[k];
        acc += g_dinv[s] * xw[(size_t)s * 256 + c];
    }
    float v = fmaxf(acc * dn + bias[c], 0.0f);
    unsigned idx = (unsigned)(n * 256 + c);
    unsigned w = g_mask2[idx >> 5];
    out[idx] = ((w >> (idx & 31)) & 1u) ? v * 2.0f : 0.0f;
}

// ---------------- launch -----------------------------------------------------
extern "C" void kernel_launch(void* const* d_in, const int* in_sizes, int n_in,
                              void* d_out, int out_size)
{
    const float* x  = (const float*)d_in[0];
    const void*  ei = d_in[1];
    const float* W1 = (const float*)d_in[2];
    const float* b1 = (const float*)d_in[3];
    const float* W2 = (const float*)d_in[4];
    const float* b2 = (const float*)d_in[5];
    float* out = (float*)d_out;

    float *p_aggx, *p_h1lo, *p_h1hi, *p_xw2, *p_w1t, *p_w2tlo, *p_w2thi;
    unsigned *p_m1, *p_m2;
    cudaGetSymbolAddress((void**)&p_aggx,  g_aggx);
    cudaGetSymbolAddress((void**)&p_h1lo,  g_h1lo);
    cudaGetSymbolAddress((void**)&p_h1hi,  g_h1hi);
    cudaGetSymbolAddress((void**)&p_xw2,   g_xw2);
    cudaGetSymbolAddress((void**)&p_w1t,   g_w1t);
    cudaGetSymbolAddress((void**)&p_w2tlo, g_w2tlo);
    cudaGetSymbolAddress((void**)&p_w2thi, g_w2thi);
    cudaGetSymbolAddress((void**)&p_m1,    g_mask1);
    cudaGetSymbolAddress((void**)&p_m2,    g_mask2);

    constexpr int SMEMB = (128 * SROW + 64 * SROW) * 4;  // 199,680 B
    cudaFuncSetAttribute(gemm_kernel<4, 1>, cudaFuncAttributeMaxDynamicSharedMemorySize, SMEMB);
    cudaFuncSetAttribute(gemm_kernel<2, 0>, cudaFuncAttributeMaxDynamicSharedMemorySize, SMEMB);
    cudaFuncSetAttribute(gemm_kernel<2, 2>, cudaFuncAttributeMaxDynamicSharedMemorySize, SMEMB);

    // dropout keys: split(key(42)), partitionable (validated R1/R3)
    unsigned dk1_0, dk1_1, dk2_0, dk2_1;
    tf2x32(0u, 42u, 0u, 0u, dk1_0, dk1_1);
    tf2x32(0u, 42u, 0u, 1u, dk2_0, dk2_1);

    // side stream for independent work (created once; capture-safe pattern)
    static cudaStream_t s2 = nullptr;
    static cudaEvent_t ev_fork = nullptr, ev_join = nullptr;
    if (s2 == nullptr) {
        cudaStreamCreateWithFlags(&s2, cudaStreamNonBlocking);
        cudaEventCreateWithFlags(&ev_fork, cudaEventDisableTiming);
        cudaEventCreateWithFlags(&ev_join, cudaEventDisableTiming);
    }

    // fork: side stream does weight transposes + dropout masks
    cudaEventRecord(ev_fork, 0);
    cudaStreamWaitEvent(s2, ev_fork, 0);
    {
        dim3 blk(32, 8);
        transpose3_kernel<<<dim3(16, 8, 3), blk, 0, s2>>>(W1, W2);
        mask_kernel<<<20000, 256, 0, s2>>>(p_m1, dk1_0, dk1_1);
        mask_kernel<<<10000, 256, 0, s2>>>(p_m2, dk2_0, dk2_1);
    }
    cudaEventRecord(ev_join, s2);

    // main stream: graph preprocessing + aggregate-first layer 1
    init_kernel<<<40, 256>>>((const int*)ei);
    count_kernel<<<(N_EDGES + 255) / 256, 256>>>(ei);
    scan_kernel<<<1, 1024>>>();
    fill_kernel<<<(N_EDGES + 255) / 256, 256>>>(ei);
    aggx_kernel<<<N_NODES, 256>>>(x);

    cudaStreamWaitEvent(0, ev_join, 0);

    // Layer 1 GEMM: (ÂX) @ W1 + b1, relu, dropout -> h1 (lo/hi split)
    gemm_kernel<4, 1><<<dim3(2, 79), 256, SMEMB>>>(
        p_aggx, p_w1t, p_h1lo, p_h1hi, b1, p_m1, N_NODES);

    // Layer 2 GEMM: h1 @ W2 as two K=256 accumulate passes
    gemm_kernel<2, 0><<<dim3(2, 79), 256, SMEMB>>>(
        p_h1lo, p_w2tlo, p_xw2, nullptr, nullptr, nullptr, N_NODES);
    gemm_kernel<2, 2><<<dim3(2, 79), 256, SMEMB>>>(
        p_h1hi, p_w2thi, p_xw2, nullptr, nullptr, nullptr, N_NODES);

    // Layer 2 aggregate + bias + relu + dropout -> out
    agg2_kernel<<<N_NODES, 256>>>(p_xw2, b2, out);
}

// round 5
// speedup vs baseline: 1.4361x; 1.4361x over previous
#include <cuda_runtime.h>
#include <stdint.h>

#define N_NODES 10000
#define N_EDGES 160000
#define M_PAD   10112           // 79 * 128

// ---------------- device scratch (no allocations allowed) ----------------
__device__ float g_aggx[M_PAD * 256];     // ÂX, tf32 bits
__device__ float g_h1  [M_PAD * 512];     // layer-1 out, tf32 bits
__device__ float g_xw2 [N_NODES * 256];   // h1 @ W2, f32
__device__ float g_w1t [512 * 256];       // W1^T, tf32 bits
__device__ float g_w2t [256 * 512];       // W2^T, tf32 bits
__device__ unsigned g_mask1[160000];      // 5.12M dropout bits (layer 1)
__device__ float g_dinv[N_NODES];
__device__ int   g_cnt[N_NODES];
__device__ int   g_off[N_NODES + 1];
__device__ int   g_cur[N_NODES];
__device__ int   g_csr[N_EDGES];
__device__ int   g_is64 = 1;

// ---------------- PTX helpers ----------------
__device__ __forceinline__ uint32_t smem_to_u32(const void* p) {
    uint32_t a;
    asm("{ .reg .u64 t; cvta.to.shared.u64 t, %1; cvt.u32.u64 %0, t; }" : "=r"(a) : "l"(p));
    return a;
}
__device__ __forceinline__ uint32_t f2tf32(float f) {
    uint32_t r;
    asm("cvt.rna.tf32.f32 %0, %1;" : "=r"(r) : "f"(f));
    return r;
}
__device__ __forceinline__ float tf32bits(float f) {  // value whose bits are tf32(f)
    return __uint_as_float(f2tf32(f));
}
__device__ __forceinline__ void cp_async16(uint32_t dst, const void* src) {
    asm volatile("cp.async.cg.shared.global [%0], [%1], 16;" :: "r"(dst), "l"(src));
}
#define CP_COMMIT()  asm volatile("cp.async.commit_group;" ::: "memory")
#define CP_WAIT(n)   asm volatile("cp.async.wait_group %0;" :: "n"(n) : "memory")

// m16n8k8 tf32 MMA, row.col, fp32 accumulate
__device__ __forceinline__ void mma_tf32(float* d, const uint32_t* a, const uint32_t* b) {
    asm volatile(
        "mma.sync.aligned.m16n8k8.row.col.f32.tf32.tf32.f32 "
        "{%0,%1,%2,%3},{%4,%5,%6,%7},{%8,%9},{%0,%1,%2,%3};"
        : "+f"(d[0]), "+f"(d[1]), "+f"(d[2]), "+f"(d[3])
        : "r"(a[0]), "r"(a[1]), "r"(a[2]), "r"(a[3]), "r"(b[0]), "r"(b[1]));
}

// ---------------- threefry2x32 (JAX-compatible, validated R1/R3) ---------
#define TF_ROUND(v0, v1, r) do { (v0) += (v1); (v1) = ((v1) << (r)) | ((v1) >> (32 - (r))); (v1) ^= (v0); } while (0)
__host__ __device__ inline void tf2x32(unsigned k0, unsigned k1,
                                       unsigned x0, unsigned x1,
                                       unsigned& o0, unsigned& o1) {
    unsigned ks0 = k0, ks1 = k1, ks2 = k0 ^ k1 ^ 0x1BD11BDAu;
    unsigned v0 = x0 + ks0, v1 = x1 + ks1;
    TF_ROUND(v0, v1, 13); TF_ROUND(v0, v1, 15); TF_ROUND(v0, v1, 26); TF_ROUND(v0, v1, 6);
    v0 += ks1; v1 += ks2 + 1u;
    TF_ROUND(v0, v1, 17); TF_ROUND(v0, v1, 29); TF_ROUND(v0, v1, 16); TF_ROUND(v0, v1, 24);
    v0 += ks2; v1 += ks0 + 2u;
    TF_ROUND(v0, v1, 13); TF_ROUND(v0, v1, 15); TF_ROUND(v0, v1, 26); TF_ROUND(v0, v1, 6);
    v0 += ks0; v1 += ks1 + 3u;
    TF_ROUND(v0, v1, 17); TF_ROUND(v0, v1, 29); TF_ROUND(v0, v1, 16); TF_ROUND(v0, v1, 24);
    v0 += ks1; v1 += ks2 + 4u;
    TF_ROUND(v0, v1, 13); TF_ROUND(v0, v1, 15); TF_ROUND(v0, v1, 26); TF_ROUND(v0, v1, 6);
    v0 += ks2; v1 += ks0 + 5u;
    o0 = v0; o1 = v1;
}

// ---------------- preprocessing --------------------------------------------
__device__ inline int edge_at(const void* ei, int pos) {
    if (g_is64) return (int)((const long long*)ei)[pos];
    return ((const int*)ei)[pos];
}
__global__ void init_kernel(const int* __restrict__ ei32) {
    int t = blockIdx.x * blockDim.x + threadIdx.x;
    if (t < N_NODES) g_cnt[t] = 0;
    if (t < 1024) {
        if (ei32[t * 2 + 1] != 0) g_is64 = 0;
    }
}
__global__ void count_kernel(const void* __restrict__ ei) {
    int e = blockIdx.x * blockDim.x + threadIdx.x;
    if (e >= N_EDGES) return;
    atomicAdd(&g_cnt[edge_at(ei, N_EDGES + e)], 1);
}
__global__ void scan_kernel() {
    __shared__ int sh[1024];
    int carry = 0;
    for (int base = 0; base < N_NODES; base += 1024) {
        int i = base + (int)threadIdx.x;
        int v = (i < N_NODES) ? g_cnt[i] : 0;
        if (i < N_NODES) g_dinv[i] = rsqrtf((float)(v + 1));
        sh[threadIdx.x] = v;
        __syncthreads();
        for (int off = 1; off < 1024; off <<= 1) {
            int t = (threadIdx.x >= (unsigned)off) ? sh[threadIdx.x - off] : 0;
            __syncthreads();
            sh[threadIdx.x] += t;
            __syncthreads();
        }
        if (i < N_NODES) {
            int excl = sh[threadIdx.x] - v + carry;
            g_off[i] = excl;
            g_cur[i] = excl;
        }
        carry += sh[1023];
        __syncthreads();
    }
    if (threadIdx.x == 0) g_off[N_NODES] = carry;
}
__global__ void fill_kernel(const void* __restrict__ ei) {
    int e = blockIdx.x * blockDim.x + threadIdx.x;
    if (e >= N_EDGES) return;
    int s = edge_at(ei, e);
    int d = edge_at(ei, N_EDGES + e);
    g_csr[atomicAdd(&g_cur[d], 1)] = s;
}

// two transposes -> tf32 bits. z=0: W1[256,512]->w1t[512,256]; z=1: W2[512,256]->w2t[256,512]
__global__ void transpose2_kernel(const float* __restrict__ W1,
                                  const float* __restrict__ W2) {
    __shared__ float tile[32][33];
    int z = blockIdx.z;
    const float* src = (z == 0) ? W1 : W2;
    float* dst = (z == 0) ? g_w1t : g_w2t;
    int R = (z == 0) ? 256 : 512;   // src rows (K of gemm)
    int C = (z == 0) ? 512 : 256;   // src cols (N of gemm)
    if (blockIdx.x * 32 >= C || blockIdx.y * 32 >= R) return;
    int c0 = blockIdx.x * 32, r0 = blockIdx.y * 32;
#pragma unroll
    for (int i = 0; i < 32; i += 8) {
        int r = r0 + threadIdx.y + i, c = c0 + threadIdx.x;
        tile[threadIdx.y + i][threadIdx.x] = src[(size_t)r * C + c];
    }
    __syncthreads();
#pragma unroll
    for (int i = 0; i < 32; i += 8) {
        int c = c0 + threadIdx.y + i, r = r0 + threadIdx.x;
        dst[(size_t)c * R + r] = tf32bits(tile[threadIdx.x][threadIdx.y + i]);
    }
}

// dropout bitmask (layer 1): one thread per element, ballot into words
__global__ void mask_kernel(unsigned* __restrict__ mask, unsigned k0, unsigned k1) {
    unsigned i = blockIdx.x * 256u + threadIdx.x;
    unsigned y0, y1;
    tf2x32(k0, k1, 0u, i, y0, y1);
    unsigned bits = y0 ^ y1;
    float u = __uint_as_float((bits >> 9) | 0x3f800000u) - 1.0f;
    unsigned ball = __ballot_sync(0xffffffffu, u < 0.5f);
    if ((threadIdx.x & 31) == 0) mask[i >> 5] = ball;
}

// ---------------- tensor-core tf32 GEMM (R3 skeleton, pre-converted inputs) ----
// C[M,N_OUT] = A[M,K_TOT] @ Bt[N_OUT,K_TOT]^T. A/Bt hold tf32 BITS.
// BM=128, BN=128, BK=32, 8 warps 4(m)x2(n), warp tile 32x64.
// EPI 0: plain f32 store. EPI 1: bias+relu+mask-dropout, store tf32 bits.
#define SROW 36
#define S_BUF (256 * SROW)

template <int N_OUT, int K_TOT, int EPI>
__global__ void __launch_bounds__(256, 2)
mma_gemm_kernel(const float* __restrict__ A, const float* __restrict__ Bt,
                float* __restrict__ C, const float* __restrict__ bias,
                const unsigned* __restrict__ mask, int M)
{
    extern __shared__ float sm[];
    const int tid = threadIdx.x;
    const int wid = tid >> 5, lane = tid & 31;
    const int g = lane >> 2, tig = lane & 3;
    const int wm = wid >> 1, wn = wid & 1;
    const int bm = blockIdx.y * 128;
    const int bn = blockIdx.x * 128;
    constexpr int NBK = K_TOT / 32;

    const uint32_t sbase = smem_to_u32(sm);

    float acc[2][8][4];
#pragma unroll
    for (int mi = 0; mi < 2; mi++)
#pragma unroll
        for (int ni = 0; ni < 8; ni++)
#pragma unroll
            for (int j = 0; j < 4; j++) acc[mi][ni][j] = 0.0f;

    auto load_tile = [&](int kc, int buf) {
#pragma unroll
        for (int r = 0; r < 4; r++) {
            int chunk = r * 256 + tid;
            int row = chunk >> 3;
            int f4  = chunk & 7;
            int gr = bm + row; if (gr >= M) gr = M - 1;
            uint32_t dA = sbase + (uint32_t)(buf * S_BUF + row * SROW + f4 * 4) * 4u;
            cp_async16(dA, A + (size_t)gr * K_TOT + kc * 32 + f4 * 4);
            int gn = bn + row;
            uint32_t dB = sbase + (uint32_t)(buf * S_BUF + (128 + row) * SROW + f4 * 4) * 4u;
            cp_async16(dB, Bt + (size_t)gn * K_TOT + kc * 32 + f4 * 4);
        }
    };

    load_tile(0, 0);
    CP_COMMIT();

    for (int kc = 0; kc < NBK; kc++) {
        int buf = kc & 1;
        if (kc + 1 < NBK) {
            load_tile(kc + 1, buf ^ 1);
            CP_COMMIT();
            CP_WAIT(1);
        } else {
            CP_WAIT(0);
        }
        __syncthreads();

        const uint32_t* As = (const uint32_t*)(sm + buf * S_BUF);
        const uint32_t* Bs = As + 128 * SROW;
        const int rm = wm * 32;
        const int cn = wn * 64;

#pragma unroll
        for (int s = 0; s < 4; s++) {
            int k0 = s * 8;
            uint32_t af[2][4];
#pragma unroll
            for (int mi = 0; mi < 2; mi++) {
                int r0 = rm + mi * 16 + g;
                af[mi][0] = As[r0 * SROW + k0 + tig];
                af[mi][1] = As[(r0 + 8) * SROW + k0 + tig];
                af[mi][2] = As[r0 * SROW + k0 + tig + 4];
                af[mi][3] = As[(r0 + 8) * SROW + k0 + tig + 4];
            }
#pragma unroll
            for (int ni = 0; ni < 8; ni++) {
                int n0 = cn + ni * 8 + g;
                uint32_t bf[2];
                bf[0] = Bs[n0 * SROW + k0 + tig];
                bf[1] = Bs[n0 * SROW + k0 + tig + 4];
                mma_tf32(acc[0][ni], af[0], bf);
                mma_tf32(acc[1][ni], af[1], bf);
            }
        }
        __syncthreads();
    }

    // epilogue
#pragma unroll
    for (int mi = 0; mi < 2; mi++) {
#pragma unroll
        for (int h = 0; h < 2; h++) {
            int m = bm + wm * 32 + mi * 16 + g + h * 8;
            if (m >= M) continue;
#pragma unroll
            for (int ni = 0; ni < 8; ni++) {
                int n0 = bn + wn * 64 + ni * 8 + tig * 2;
                float v0 = acc[mi][ni][h * 2 + 0];
                float v1 = acc[mi][ni][h * 2 + 1];
                if (EPI == 0) {
                    *(float2*)(C + (size_t)m * N_OUT + n0) = make_float2(v0, v1);
                } else {
                    float r0v = fmaxf(v0 + bias[n0], 0.0f);
                    float r1v = fmaxf(v1 + bias[n0 + 1], 0.0f);
                    unsigned idx = (unsigned)m * (unsigned)N_OUT + (unsigned)n0;
                    unsigned w = mask[idx >> 5];
                    r0v = ((w >> (idx & 31)) & 1u) ? r0v * 2.0f : 0.0f;
                    r1v = ((w >> ((idx + 1) & 31)) & 1u) ? r1v * 2.0f : 0.0f;
                    *(float2*)(C + (size_t)m * N_OUT + n0) =
                        make_float2(tf32bits(r0v), tf32bits(r1v));
                }
            }
        }
    }
}

// ---------------- aggregations ----------------------------------------------
// aggx: ÂX on the 256-ch input, output tf32 bits
__global__ void aggx_kernel(const float* __restrict__ x) {
    int n = blockIdx.x, c = threadIdx.x;
    float dn = g_dinv[n];
    float acc = dn * x[(size_t)n * 256 + c];
    int k0 = g_off[n], k1 = g_off[n + 1];
    for (int k = k0; k < k1; k++) {
        int s = g_csr[k];
        acc += g_dinv[s] * x[(size_t)s * 256 + c];
    }
    g_aggx[(size_t)n * 256 + c] = tf32bits(acc * dn);
}

// agg2: Â(h1 W2) + bias, relu, inline threefry dropout -> out (f32)
__global__ void agg2_kernel(const float* __restrict__ xw,
                            const float* __restrict__ bias,
                            float* __restrict__ out,
                            unsigned dk0, unsigned dk1) {
    int n = blockIdx.x, c = threadIdx.x;
    float dn = g_dinv[n];
    float acc = dn * xw[(size_t)n * 256 + c];
    int k0 = g_off[n], k1 = g_off[n + 1];
    for (int k = k0; k < k1; k++) {
        int s = g_csr[k];
        acc += g_dinv[s] * xw[(size_t)s * 256 + c];
    }
    float v = fmaxf(acc * dn + bias[c], 0.0f);
    unsigned i = (unsigned)(n * 256 + c);
    unsigned y0, y1;
    tf2x32(dk0, dk1, 0u, i, y0, y1);
    unsigned bits = y0 ^ y1;
    float u = __uint_as_float((bits >> 9) | 0x3f800000u) - 1.0f;
    out[i] = (u < 0.5f) ? v * 2.0f : 0.0f;
}

// ---------------- launch -----------------------------------------------------
extern "C" void kernel_launch(void* const* d_in, const int* in_sizes, int n_in,
                              void* d_out, int out_size)
{
    const float* x  = (const float*)d_in[0];
    const void*  ei = d_in[1];
    const float* W1 = (const float*)d_in[2];
    const float* b1 = (const float*)d_in[3];
    const float* W2 = (const float*)d_in[4];
    const float* b2 = (const float*)d_in[5];
    float* out = (float*)d_out;

    float *p_aggx, *p_h1, *p_xw2, *p_w1t, *p_w2t;
    unsigned* p_m1;
    cudaGetSymbolAddress((void**)&p_aggx, g_aggx);
    cudaGetSymbolAddress((void**)&p_h1,   g_h1);
    cudaGetSymbolAddress((void**)&p_xw2,  g_xw2);
    cudaGetSymbolAddress((void**)&p_w1t,  g_w1t);
    cudaGetSymbolAddress((void**)&p_w2t,  g_w2t);
    cudaGetSymbolAddress((void**)&p_m1,   g_mask1);

    constexpr int SMEMB = 2 * S_BUF * 4;  // 73,728 B
    cudaFuncSetAttribute(mma_gemm_kernel<512, 256, 1>,
                         cudaFuncAttributeMaxDynamicSharedMemorySize, SMEMB);
    cudaFuncSetAttribute(mma_gemm_kernel<256, 512, 0>,
                         cudaFuncAttributeMaxDynamicSharedMemorySize, SMEMB);

    // dropout keys: split(key(42)), partitionable (validated)
    unsigned dk1_0, dk1_1, dk2_0, dk2_1;
    tf2x32(0u, 42u, 0u, 0u, dk1_0, dk1_1);
    tf2x32(0u, 42u, 0u, 1u, dk2_0, dk2_1);

    static cudaStream_t s2 = nullptr;
    static cudaEvent_t ev_fork = nullptr, ev_join = nullptr;
    if (s2 == nullptr) {
        cudaStreamCreateWithFlags(&s2, cudaStreamNonBlocking);
        cudaEventCreateWithFlags(&ev_fork, cudaEventDisableTiming);
        cudaEventCreateWithFlags(&ev_join, cudaEventDisableTiming);
    }

    // fork side stream: weight transposes (tf32) + layer-1 dropout mask
    cudaEventRecord(ev_fork, 0);
    cudaStreamWaitEvent(s2, ev_fork, 0);
    {
        dim3 blk(32, 8);
        transpose2_kernel<<<dim3(16, 16, 2), blk, 0, s2>>>(W1, W2);
        mask_kernel<<<20000, 256, 0, s2>>>(p_m1, dk1_0, dk1_1);
    }
    cudaEventRecord(ev_join, s2);

    // main stream: graph preprocessing + aggregate-first
    init_kernel<<<40, 256>>>((const int*)ei);
    count_kernel<<<(N_EDGES + 255) / 256, 256>>>(ei);
    scan_kernel<<<1, 1024>>>();
    fill_kernel<<<(N_EDGES + 255) / 256, 256>>>(ei);
    aggx_kernel<<<N_NODES, 256>>>(x);

    cudaStreamWaitEvent(0, ev_join, 0);

    // Layer 1: (ÂX) @ W1, fused bias+relu+dropout -> h1 (tf32 bits)
    mma_gemm_kernel<512, 256, 1><<<dim3(4, 79), 256, SMEMB>>>(
        p_aggx, p_w1t, p_h1, b1, p_m1, N_NODES);

    // Layer 2 GEMM: h1 @ W2 -> xw2 (f32)
    mma_gemm_kernel<256, 512, 0><<<dim3(2, 79), 256, SMEMB>>>(
        p_h1, p_w2t, p_xw2, nullptr, nullptr, N_NODES);

    // Layer 2 aggregate + bias + relu + dropout -> out
    agg2_kernel<<<N_NODES, 256>>>(p_xw2, b2, out, dk2_0, dk2_1);
}

// round 6
// speedup vs baseline: 1.7875x; 1.2447x over previous
#include <cuda_runtime.h>
#include <cuda_fp16.h>
#include <stdint.h>

#define N_NODES 10000
#define N_EDGES 160000
#define M_PAD   10112           // 79 * 128
#define SPLIT_M 5120            // 40 tiles for chain A, 39 for chain B

// ---------------- device scratch (no allocations allowed) ----------------
__device__ __half g_aggx[M_PAD * 256];    // ÂX, fp16
__device__ __half g_h1  [M_PAD * 512];    // layer-1 out, fp16
__device__ float  g_xw2 [N_NODES * 256];  // h1 @ W2, f32
__device__ __half g_w1t [512 * 256];      // W1^T, fp16
__device__ __half g_w2t [256 * 512];      // W2^T, fp16
__device__ unsigned g_mask1[160000];      // 5.12M dropout bits (layer 1)
__device__ float g_dinv[N_NODES];
__device__ int   g_cnt[N_NODES];          // zero at load; scan re-zeroes each run
__device__ int   g_off[N_NODES + 1];
__device__ int   g_cur[N_NODES];
__device__ int   g_csr[N_EDGES];

// ---------------- PTX helpers ----------------
__device__ __forceinline__ uint32_t smem_to_u32(const void* p) {
    uint32_t a;
    asm("{ .reg .u64 t; cvta.to.shared.u64 t, %1; cvt.u32.u64 %0, t; }" : "=r"(a) : "l"(p));
    return a;
}
__device__ __forceinline__ void cp_async16(uint32_t dst, const void* src) {
    asm volatile("cp.async.cg.shared.global [%0], [%1], 16;" :: "r"(dst), "l"(src));
}
#define CP_COMMIT()  asm volatile("cp.async.commit_group;" ::: "memory")
#define CP_WAIT(n)   asm volatile("cp.async.wait_group %0;" :: "n"(n) : "memory")

// m16n8k16 fp16 MMA, row.col, fp32 accumulate (same reg signature as tf32 k8)
__device__ __forceinline__ void mma_f16(float* d, const uint32_t* a, const uint32_t* b) {
    asm volatile(
        "mma.sync.aligned.m16n8k16.row.col.f32.f16.f16.f32 "
        "{%0,%1,%2,%3},{%4,%5,%6,%7},{%8,%9},{%0,%1,%2,%3};"
        : "+f"(d[0]), "+f"(d[1]), "+f"(d[2]), "+f"(d[3])
        : "r"(a[0]), "r"(a[1]), "r"(a[2]), "r"(a[3]), "r"(b[0]), "r"(b[1]));
}

// ---------------- threefry2x32 (JAX-compatible, validated) ----------------
#define TF_ROUND(v0, v1, r) do { (v0) += (v1); (v1) = ((v1) << (r)) | ((v1) >> (32 - (r))); (v1) ^= (v0); } while (0)
__host__ __device__ inline void tf2x32(unsigned k0, unsigned k1,
                                       unsigned x0, unsigned x1,
                                       unsigned& o0, unsigned& o1) {
    unsigned ks0 = k0, ks1 = k1, ks2 = k0 ^ k1 ^ 0x1BD11BDAu;
    unsigned v0 = x0 + ks0, v1 = x1 + ks1;
    TF_ROUND(v0, v1, 13); TF_ROUND(v0, v1, 15); TF_ROUND(v0, v1, 26); TF_ROUND(v0, v1, 6);
    v0 += ks1; v1 += ks2 + 1u;
    TF_ROUND(v0, v1, 17); TF_ROUND(v0, v1, 29); TF_ROUND(v0, v1, 16); TF_ROUND(v0, v1, 24);
    v0 += ks2; v1 += ks0 + 2u;
    TF_ROUND(v0, v1, 13); TF_ROUND(v0, v1, 15); TF_ROUND(v0, v1, 26); TF_ROUND(v0, v1, 6);
    v0 += ks0; v1 += ks1 + 3u;
    TF_ROUND(v0, v1, 17); TF_ROUND(v0, v1, 29); TF_ROUND(v0, v1, 16); TF_ROUND(v0, v1, 24);
    v0 += ks1; v1 += ks2 + 4u;
    TF_ROUND(v0, v1, 13); TF_ROUND(v0, v1, 15); TF_ROUND(v0, v1, 26); TF_ROUND(v0, v1, 6);
    v0 += ks2; v1 += ks0 + 5u;
    o0 = v0; o1 = v1;
}

// ---------------- preprocessing --------------------------------------------
// warp-local int64/int32 detection: hi word of 64-bit elem e sits at int32 idx
// 2e+1 (< 2*N_EDGES, in-bounds for both dtypes). int64 indices < 2^31 -> hi==0.
__device__ __forceinline__ bool detect_is64(const void* ei, int e) {
    unsigned hiw = ((const unsigned*)ei)[2u * (unsigned)e + 1u];
    return !__any_sync(0xffffffffu, hiw != 0u);
}

__global__ void count_kernel(const void* __restrict__ ei) {
    int e = blockIdx.x * blockDim.x + threadIdx.x;   // grid exactly covers N_EDGES
    bool is64 = detect_is64(ei, e);
    int d = is64 ? (int)((const long long*)ei)[N_EDGES + e]
                 : ((const int*)ei)[N_EDGES + e];
    atomicAdd(&g_cnt[d], 1);
}

__global__ void scan_kernel() {
    __shared__ int sh[1024];
    int carry = 0;
    for (int base = 0; base < N_NODES; base += 1024) {
        int i = base + (int)threadIdx.x;
        int v = (i < N_NODES) ? g_cnt[i] : 0;
        if (i < N_NODES) {
            g_dinv[i] = rsqrtf((float)(v + 1));
            g_cnt[i] = 0;                      // self-clear for next graph replay
        }
        sh[threadIdx.x] = v;
        __syncthreads();
        for (int off = 1; off < 1024; off <<= 1) {
            int t = (threadIdx.x >= (unsigned)off) ? sh[threadIdx.x - off] : 0;
            __syncthreads();
            sh[threadIdx.x] += t;
            __syncthreads();
        }
        if (i < N_NODES) {
            int excl = sh[threadIdx.x] - v + carry;
            g_off[i] = excl;
            g_cur[i] = excl;
        }
        carry += sh[1023];
        __syncthreads();
    }
    if (threadIdx.x == 0) g_off[N_NODES] = carry;
}

__global__ void fill_kernel(const void* __restrict__ ei) {
    int e = blockIdx.x * blockDim.x + threadIdx.x;
    bool is64 = detect_is64(ei, e);
    int s, d;
    if (is64) {
        s = (int)((const long long*)ei)[e];
        d = (int)((const long long*)ei)[N_EDGES + e];
    } else {
        s = ((const int*)ei)[e];
        d = ((const int*)ei)[N_EDGES + e];
    }
    g_csr[atomicAdd(&g_cur[d], 1)] = s;
}

// two transposes -> fp16. z=0: W1[256,512]->w1t[512,256]; z=1: W2[512,256]->w2t[256,512]
__global__ void transpose2_kernel(const float* __restrict__ W1,
                                  const float* __restrict__ W2) {
    __shared__ float tile[32][33];
    int z = blockIdx.z;
    const float* src = (z == 0) ? W1 : W2;
    __half* dst = (z == 0) ? g_w1t : g_w2t;
    int R = (z == 0) ? 256 : 512;
    int C = (z == 0) ? 512 : 256;
    if (blockIdx.x * 32 >= C || blockIdx.y * 32 >= R) return;
    int c0 = blockIdx.x * 32, r0 = blockIdx.y * 32;
#pragma unroll
    for (int i = 0; i < 32; i += 8) {
        int r = r0 + threadIdx.y + i, c = c0 + threadIdx.x;
        tile[threadIdx.y + i][threadIdx.x] = src[(size_t)r * C + c];
    }
    __syncthreads();
#pragma unroll
    for (int i = 0; i < 32; i += 8) {
        int c = c0 + threadIdx.y + i, r = r0 + threadIdx.x;
        dst[(size_t)c * R + r] = __float2half(tile[threadIdx.x][threadIdx.y + i]);
    }
}

// dropout bitmask (layer 1)
__global__ void mask_kernel(unsigned* __restrict__ mask, unsigned k0, unsigned k1) {
    unsigned i = blockIdx.x * 256u + threadIdx.x;
    unsigned y0, y1;
    tf2x32(k0, k1, 0u, i, y0, y1);
    unsigned bits = y0 ^ y1;
    float u = __uint_as_float((bits >> 9) | 0x3f800000u) - 1.0f;
    unsigned ball = __ballot_sync(0xffffffffu, u < 0.5f);
    if ((threadIdx.x & 31) == 0) mask[i >> 5] = ball;
}

// ---------------- fp16 tensor-core GEMM -------------------------------------
// C[M,N_OUT] = A[M,K_TOT] @ Bt[N_OUT,K_TOT]^T, A/Bt fp16, fp32 accumulate.
// BM=128, BN=128, BK=64 halves, 8 warps 4(m)x2(n), warp tile 32x64.
// smem rows: 64 halves data + pad = 36 u32 (conflict-free fragment LDS).
// EPI 0: f32 store. EPI 1: bias+relu+mask-dropout, store fp16.
#define SROW32 36
#define S_BUF32 (256 * SROW32)

template <int N_OUT, int K_TOT, int EPI>
__global__ void __launch_bounds__(256, 2)
hgemm_kernel(const __half* __restrict__ A, const __half* __restrict__ Bt,
             void* __restrict__ Cv, const float* __restrict__ bias,
             const unsigned* __restrict__ mask, int M, int m0)
{
    extern __shared__ uint32_t sm32[];
    const int tid = threadIdx.x;
    const int wid = tid >> 5, lane = tid & 31;
    const int g = lane >> 2, tig = lane & 3;
    const int wm = wid >> 1, wn = wid & 1;
    const int bm = m0 + blockIdx.y * 128;
    const int bn = blockIdx.x * 128;
    constexpr int NBK = K_TOT / 64;

    const uint32_t sbase = smem_to_u32(sm32);

    float acc[2][8][4];
#pragma unroll
    for (int mi = 0; mi < 2; mi++)
#pragma unroll
        for (int ni = 0; ni < 8; ni++)
#pragma unroll
            for (int j = 0; j < 4; j++) acc[mi][ni][j] = 0.0f;

    auto load_tile = [&](int kc, int buf) {
#pragma unroll
        for (int r = 0; r < 4; r++) {
            int chunk = r * 256 + tid;       // 0..1023
            int row = chunk >> 3;            // 0..127
            int f4  = chunk & 7;             // 16B chunk within 128B row
            int gr = bm + row; if (gr >= M) gr = M - 1;
            uint32_t dA = sbase + (uint32_t)(buf * S_BUF32 + row * SROW32 + f4 * 4) * 4u;
            cp_async16(dA, A + (size_t)gr * K_TOT + kc * 64 + f4 * 8);
            int gn = bn + row;
            uint32_t dB = sbase + (uint32_t)(buf * S_BUF32 + (128 + row) * SROW32 + f4 * 4) * 4u;
            cp_async16(dB, Bt + (size_t)gn * K_TOT + kc * 64 + f4 * 8);
        }
    };

    load_tile(0, 0);
    CP_COMMIT();

    for (int kc = 0; kc < NBK; kc++) {
        int buf = kc & 1;
        if (kc + 1 < NBK) {
            load_tile(kc + 1, buf ^ 1);
            CP_COMMIT();
            CP_WAIT(1);
        } else {
            CP_WAIT(0);
        }
        __syncthreads();

        const uint32_t* As = sm32 + buf * S_BUF32;
        const uint32_t* Bs = As + 128 * SROW32;
        const int rm = wm * 32;
        const int cn = wn * 64;

#pragma unroll
        for (int s = 0; s < 4; s++) {       // 4 x k16 per BK=64
            int k0u = s * 8;                // u32 offset in row
            uint32_t af[2][4];
#pragma unroll
            for (int mi = 0; mi < 2; mi++) {
                int r0 = rm + mi * 16 + g;
                af[mi][0] = As[r0 * SROW32 + k0u + tig];
                af[mi][1] = As[(r0 + 8) * SROW32 + k0u + tig];
                af[mi][2] = As[r0 * SROW32 + k0u + 4 + tig];
                af[mi][3] = As[(r0 + 8) * SROW32 + k0u + 4 + tig];
            }
#pragma unroll
            for (int ni = 0; ni < 8; ni++) {
                int n0 = cn + ni * 8 + g;
                uint32_t bf[2];
                bf[0] = Bs[n0 * SROW32 + k0u + tig];
                bf[1] = Bs[n0 * SROW32 + k0u + 4 + tig];
                mma_f16(acc[0][ni], af[0], bf);
                mma_f16(acc[1][ni], af[1], bf);
            }
        }
        __syncthreads();
    }

    // epilogue
#pragma unroll
    for (int mi = 0; mi < 2; mi++) {
#pragma unroll
        for (int h = 0; h < 2; h++) {
            int m = bm + wm * 32 + mi * 16 + g + h * 8;
            if (m >= M) continue;
#pragma unroll
            for (int ni = 0; ni < 8; ni++) {
                int n0 = bn + wn * 64 + ni * 8 + tig * 2;
                float v0 = acc[mi][ni][h * 2 + 0];
                float v1 = acc[mi][ni][h * 2 + 1];
                if (EPI == 0) {
                    *(float2*)((float*)Cv + (size_t)m * N_OUT + n0) = make_float2(v0, v1);
                } else {
                    float r0v = fmaxf(v0 + bias[n0], 0.0f);
                    float r1v = fmaxf(v1 + bias[n0 + 1], 0.0f);
                    unsigned idx = (unsigned)m * (unsigned)N_OUT + (unsigned)n0;
                    unsigned w = mask[idx >> 5];
                    r0v = ((w >> (idx & 31)) & 1u) ? r0v * 2.0f : 0.0f;
                    r1v = ((w >> ((idx + 1) & 31)) & 1u) ? r1v * 2.0f : 0.0f;
                    *(__half2*)((__half*)Cv + (size_t)m * N_OUT + n0) =
                        __floats2half2_rn(r0v, r1v);
                }
            }
        }
    }
}

// ---------------- aggregations ----------------------------------------------
// aggx: ÂX on 256-ch input -> fp16; node range [base, base+gridDim.x)
__global__ void aggx_kernel(const float* __restrict__ x, int base) {
    int n = base + blockIdx.x, c = threadIdx.x;
    float dn = g_dinv[n];
    float acc = dn * x[(size_t)n * 256 + c];
    int k0 = g_off[n], k1 = g_off[n + 1];
    for (int k = k0; k < k1; k++) {
        int s = g_csr[k];
        acc += g_dinv[s] * x[(size_t)s * 256 + c];
    }
    g_aggx[(size_t)n * 256 + c] = __float2half(acc * dn);
}

// agg2: Â(h1 W2) + bias, relu, inline threefry dropout -> out (f32)
__global__ void agg2_kernel(const float* __restrict__ xw,
                            const float* __restrict__ bias,
                            float* __restrict__ out,
                            unsigned dk0, unsigned dk1) {
    int n = blockIdx.x, c = threadIdx.x;
    float dn = g_dinv[n];
    float acc = dn * xw[(size_t)n * 256 + c];
    int k0 = g_off[n], k1 = g_off[n + 1];
    for (int k = k0; k < k1; k++) {
        int s = g_csr[k];
        acc += g_dinv[s] * xw[(size_t)s * 256 + c];
    }
    float v = fmaxf(acc * dn + bias[c], 0.0f);
    unsigned i = (unsigned)(n * 256 + c);
    unsigned y0, y1;
    tf2x32(dk0, dk1, 0u, i, y0, y1);
    unsigned bits = y0 ^ y1;
    float u = __uint_as_float((bits >> 9) | 0x3f800000u) - 1.0f;
    out[i] = (u < 0.5f) ? v * 2.0f : 0.0f;
}

// ---------------- launch -----------------------------------------------------
extern "C" void kernel_launch(void* const* d_in, const int* in_sizes, int n_in,
                              void* d_out, int out_size)
{
    const float* x  = (const float*)d_in[0];
    const void*  ei = d_in[1];
    const float* W1 = (const float*)d_in[2];
    const float* b1 = (const float*)d_in[3];
    const float* W2 = (const float*)d_in[4];
    const float* b2 = (const float*)d_in[5];
    float* out = (float*)d_out;

    __half *p_aggx, *p_h1, *p_w1t, *p_w2t;
    float *p_xw2;
    unsigned* p_m1;
    cudaGetSymbolAddress((void**)&p_aggx, g_aggx);
    cudaGetSymbolAddress((void**)&p_h1,   g_h1);
    cudaGetSymbolAddress((void**)&p_xw2,  g_xw2);
    cudaGetSymbolAddress((void**)&p_w1t,  g_w1t);
    cudaGetSymbolAddress((void**)&p_w2t,  g_w2t);
    cudaGetSymbolAddress((void**)&p_m1,   g_mask1);

    constexpr int SMEMB = 2 * S_BUF32 * 4;  // 73,728 B
    cudaFuncSetAttribute(hgemm_kernel<512, 256, 1>,
                         cudaFuncAttributeMaxDynamicSharedMemorySize, SMEMB);
    cudaFuncSetAttribute(hgemm_kernel<256, 512, 0>,
                         cudaFuncAttributeMaxDynamicSharedMemorySize, SMEMB);

    // dropout keys: split(key(42)), partitionable (validated)
    unsigned dk1_0, dk1_1, dk2_0, dk2_1;
    tf2x32(0u, 42u, 0u, 0u, dk1_0, dk1_1);
    tf2x32(0u, 42u, 0u, 1u, dk2_0, dk2_1);

    static cudaStream_t s1 = nullptr, s2 = nullptr;
    static cudaEvent_t ev_fork = nullptr, ev_join = nullptr, ev_fill = nullptr, ev_b1 = nullptr;
    if (s1 == nullptr) {
        cudaStreamCreateWithFlags(&s1, cudaStreamNonBlocking);
        cudaStreamCreateWithFlags(&s2, cudaStreamNonBlocking);
        cudaEventCreateWithFlags(&ev_fork, cudaEventDisableTiming);
        cudaEventCreateWithFlags(&ev_join, cudaEventDisableTiming);
        cudaEventCreateWithFlags(&ev_fill, cudaEventDisableTiming);
        cudaEventCreateWithFlags(&ev_b1,   cudaEventDisableTiming);
    }

    // side stream: weight transposes (fp16) + layer-1 dropout mask
    cudaEventRecord(ev_fork, 0);
    cudaStreamWaitEvent(s2, ev_fork, 0);
    {
        dim3 blk(32, 8);
        transpose2_kernel<<<dim3(16, 16, 2), blk, 0, s2>>>(W1, W2);
        mask_kernel<<<20000, 256, 0, s2>>>(p_m1, dk1_0, dk1_1);
    }
    cudaEventRecord(ev_join, s2);

    // main stream: preproc (3 launches) then chain A
    count_kernel<<<N_EDGES / 256, 256>>>(ei);
    scan_kernel<<<1, 1024>>>();
    fill_kernel<<<N_EDGES / 256, 256>>>(ei);
    cudaEventRecord(ev_fill, 0);

    aggx_kernel<<<SPLIT_M, 256>>>(x, 0);                       // rows [0, 5120)

    // chain B on s1: aggxB overlaps GEMM1A
    cudaStreamWaitEvent(s1, ev_fill, 0);
    aggx_kernel<<<N_NODES - SPLIT_M, 256, 0, s1>>>(x, SPLIT_M); // rows [5120, 10000)
    cudaStreamWaitEvent(s1, ev_join, 0);
    hgemm_kernel<512, 256, 1><<<dim3(4, 39), 256, SMEMB, s1>>>(
        p_aggx, p_w1t, p_h1, b1, p_m1, N_NODES, SPLIT_M);       // rows [5120, 10112)
    cudaEventRecord(ev_b1, s1);

    // chain A on main stream
    cudaStreamWaitEvent(0, ev_join, 0);
    hgemm_kernel<512, 256, 1><<<dim3(4, 40), 256, SMEMB>>>(
        p_aggx, p_w1t, p_h1, b1, p_m1, N_NODES, 0);             // rows [0, 5120)

    // layer 2: join, GEMM2, aggregate
    cudaStreamWaitEvent(0, ev_b1, 0);
    hgemm_kernel<256, 512, 0><<<dim3(2, 79), 256, SMEMB>>>(
        p_h1, p_w2t, p_xw2, nullptr, nullptr, N_NODES, 0);
    agg2_kernel<<<N_NODES, 256>>>(p_xw2, b2, out, dk2_0, dk2_1);
}

// round 7
// speedup vs baseline: 1.9384x; 1.0844x over previous
#include <cuda_runtime.h>
#include <cuda_fp16.h>
#include <stdint.h>

#define N_NODES 10000
#define N_EDGES 160000
#define M_PAD   10112           // 79 * 128
#define SPLIT_M 5120            // 40 tiles chain A, 39 chain B

// ---------------- device scratch (no allocations allowed) ----------------
__device__ __half g_aggx[M_PAD * 256];    // ÂX, fp16
__device__ __half g_h1  [M_PAD * 512];    // layer-1 out, fp16
__device__ __half g_xw2 [N_NODES * 256];  // h1 @ W2, fp16
__device__ __half g_w1t [512 * 256];      // W1^T, fp16
__device__ __half g_w2t [256 * 512];      // W2^T, fp16
__device__ unsigned g_mask1[160000];      // 5.12M dropout bits (layer 1)
__device__ unsigned g_mask2[80000];       // 2.56M dropout bits (layer 2)
__device__ float g_dinv[N_NODES];
__device__ int   g_cnt[N_NODES];          // zero at load; scan self-clears
__device__ int   g_off[N_NODES + 1];
__device__ int   g_cur[N_NODES];
__device__ int   g_csr[N_EDGES];

// ---------------- PTX helpers ----------------
__device__ __forceinline__ uint32_t smem_to_u32(const void* p) {
    uint32_t a;
    asm("{ .reg .u64 t; cvta.to.shared.u64 t, %1; cvt.u32.u64 %0, t; }" : "=r"(a) : "l"(p));
    return a;
}
__device__ __forceinline__ void cp_async16(uint32_t dst, const void* src) {
    asm volatile("cp.async.cg.shared.global [%0], [%1], 16;" :: "r"(dst), "l"(src));
}
#define CP_COMMIT()  asm volatile("cp.async.commit_group;" ::: "memory")
#define CP_WAIT(n)   asm volatile("cp.async.wait_group %0;" :: "n"(n) : "memory")

__device__ __forceinline__ void mma_f16(float* d, const uint32_t* a, const uint32_t* b) {
    asm volatile(
        "mma.sync.aligned.m16n8k16.row.col.f32.f16.f16.f32 "
        "{%0,%1,%2,%3},{%4,%5,%6,%7},{%8,%9},{%0,%1,%2,%3};"
        : "+f"(d[0]), "+f"(d[1]), "+f"(d[2]), "+f"(d[3])
        : "r"(a[0]), "r"(a[1]), "r"(a[2]), "r"(a[3]), "r"(b[0]), "r"(b[1]));
}

// ---------------- threefry2x32 (JAX-compatible, validated) ----------------
#define TF_ROUND(v0, v1, r) do { (v0) += (v1); (v1) = ((v1) << (r)) | ((v1) >> (32 - (r))); (v1) ^= (v0); } while (0)
__host__ __device__ inline void tf2x32(unsigned k0, unsigned k1,
                                       unsigned x0, unsigned x1,
                                       unsigned& o0, unsigned& o1) {
    unsigned ks0 = k0, ks1 = k1, ks2 = k0 ^ k1 ^ 0x1BD11BDAu;
    unsigned v0 = x0 + ks0, v1 = x1 + ks1;
    TF_ROUND(v0, v1, 13); TF_ROUND(v0, v1, 15); TF_ROUND(v0, v1, 26); TF_ROUND(v0, v1, 6);
    v0 += ks1; v1 += ks2 + 1u;
    TF_ROUND(v0, v1, 17); TF_ROUND(v0, v1, 29); TF_ROUND(v0, v1, 16); TF_ROUND(v0, v1, 24);
    v0 += ks2; v1 += ks0 + 2u;
    TF_ROUND(v0, v1, 13); TF_ROUND(v0, v1, 15); TF_ROUND(v0, v1, 26); TF_ROUND(v0, v1, 6);
    v0 += ks0; v1 += ks1 + 3u;
    TF_ROUND(v0, v1, 17); TF_ROUND(v0, v1, 29); TF_ROUND(v0, v1, 16); TF_ROUND(v0, v1, 24);
    v0 += ks1; v1 += ks2 + 4u;
    TF_ROUND(v0, v1, 13); TF_ROUND(v0, v1, 15); TF_ROUND(v0, v1, 26); TF_ROUND(v0, v1, 6);
    v0 += ks2; v1 += ks0 + 5u;
    o0 = v0; o1 = v1;
}

// ---------------- preprocessing --------------------------------------------
__device__ __forceinline__ bool detect_is64(const void* ei, int e) {
    unsigned hiw = ((const unsigned*)ei)[2u * (unsigned)e + 1u];
    return !__any_sync(0xffffffffu, hiw != 0u);
}

__global__ void count_kernel(const void* __restrict__ ei) {
    int e = blockIdx.x * blockDim.x + threadIdx.x;
    bool is64 = detect_is64(ei, e);
    int d = is64 ? (int)((const long long*)ei)[N_EDGES + e]
                 : ((const int*)ei)[N_EDGES + e];
    atomicAdd(&g_cnt[d], 1);
}

// shuffle-based scan: 3 barriers per 1024-batch (was ~20)
__global__ void scan_kernel() {
    __shared__ int warp_pre[32];
    __shared__ int batch_total;
    const int lane = threadIdx.x & 31, wid = threadIdx.x >> 5;
    int carry = 0;
    for (int base = 0; base < N_NODES; base += 1024) {
        int i = base + (int)threadIdx.x;
        int v = (i < N_NODES) ? g_cnt[i] : 0;
        if (i < N_NODES) {
            g_dinv[i] = rsqrtf((float)(v + 1));
            g_cnt[i] = 0;                       // self-clear for graph replay
        }
        int incl = v;
#pragma unroll
        for (int o = 1; o < 32; o <<= 1) {
            int t = __shfl_up_sync(0xffffffffu, incl, o);
            if (lane >= o) incl += t;
        }
        if (lane == 31) warp_pre[wid] = incl;
        __syncthreads();
        if (wid == 0) {
            int ws = warp_pre[lane];
            int wincl = ws;
#pragma unroll
            for (int o = 1; o < 32; o <<= 1) {
                int t = __shfl_up_sync(0xffffffffu, wincl, o);
                if (lane >= o) wincl += t;
            }
            warp_pre[lane] = wincl - ws;         // exclusive warp prefix
            if (lane == 31) batch_total = wincl;
        }
        __syncthreads();
        int excl = incl - v + warp_pre[wid] + carry;
        if (i < N_NODES) {
            g_off[i] = excl;
            g_cur[i] = excl;
        }
        carry += batch_total;
        __syncthreads();
    }
    if (threadIdx.x == 0) g_off[N_NODES] = carry;
}

__global__ void fill_kernel(const void* __restrict__ ei) {
    int e = blockIdx.x * blockDim.x + threadIdx.x;
    bool is64 = detect_is64(ei, e);
    int s, d;
    if (is64) {
        s = (int)((const long long*)ei)[e];
        d = (int)((const long long*)ei)[N_EDGES + e];
    } else {
        s = ((const int*)ei)[e];
        d = ((const int*)ei)[N_EDGES + e];
    }
    g_csr[atomicAdd(&g_cur[d], 1)] = s;
}

// two transposes -> fp16
__global__ void transpose2_kernel(const float* __restrict__ W1,
                                  const float* __restrict__ W2) {
    __shared__ float tile[32][33];
    int z = blockIdx.z;
    const float* src = (z == 0) ? W1 : W2;
    __half* dst = (z == 0) ? g_w1t : g_w2t;
    int R = (z == 0) ? 256 : 512;
    int C = (z == 0) ? 512 : 256;
    if (blockIdx.x * 32 >= C || blockIdx.y * 32 >= R) return;
    int c0 = blockIdx.x * 32, r0 = blockIdx.y * 32;
#pragma unroll
    for (int i = 0; i < 32; i += 8) {
        int r = r0 + threadIdx.y + i, c = c0 + threadIdx.x;
        tile[threadIdx.y + i][threadIdx.x] = src[(size_t)r * C + c];
    }
    __syncthreads();
#pragma unroll
    for (int i = 0; i < 32; i += 8) {
        int c = c0 + threadIdx.y + i, r = r0 + threadIdx.x;
        dst[(size_t)c * R + r] = __float2half(tile[threadIdx.x][threadIdx.y + i]);
    }
}

// dropout bitmask
__global__ void mask_kernel(unsigned* __restrict__ mask, unsigned k0, unsigned k1) {
    unsigned i = blockIdx.x * 256u + threadIdx.x;
    unsigned y0, y1;
    tf2x32(k0, k1, 0u, i, y0, y1);
    unsigned bits = y0 ^ y1;
    float u = __uint_as_float((bits >> 9) | 0x3f800000u) - 1.0f;
    unsigned ball = __ballot_sync(0xffffffffu, u < 0.5f);
    if ((threadIdx.x & 31) == 0) mask[i >> 5] = ball;
}

// ---------------- fp16 tensor-core GEMM -------------------------------------
// EPI 0: fp16 plain store. EPI 1: bias+relu+mask-dropout, fp16 store.
#define SROW32 36
#define S_BUF32 (256 * SROW32)

template <int N_OUT, int K_TOT, int EPI>
__global__ void __launch_bounds__(256, 2)
hgemm_kernel(const __half* __restrict__ A, const __half* __restrict__ Bt,
             __half* __restrict__ C, const float* __restrict__ bias,
             const unsigned* __restrict__ mask, int M, int m0)
{
    extern __shared__ uint32_t sm32[];
    const int tid = threadIdx.x;
    const int wid = tid >> 5, lane = tid & 31;
    const int g = lane >> 2, tig = lane & 3;
    const int wm = wid >> 1, wn = wid & 1;
    const int bm = m0 + blockIdx.y * 128;
    const int bn = blockIdx.x * 128;
    constexpr int NBK = K_TOT / 64;

    const uint32_t sbase = smem_to_u32(sm32);

    float acc[2][8][4];
#pragma unroll
    for (int mi = 0; mi < 2; mi++)
#pragma unroll
        for (int ni = 0; ni < 8; ni++)
#pragma unroll
            for (int j = 0; j < 4; j++) acc[mi][ni][j] = 0.0f;

    auto load_tile = [&](int kc, int buf) {
#pragma unroll
        for (int r = 0; r < 4; r++) {
            int chunk = r * 256 + tid;
            int row = chunk >> 3;
            int f4  = chunk & 7;
            int gr = bm + row; if (gr >= M) gr = M - 1;
            uint32_t dA = sbase + (uint32_t)(buf * S_BUF32 + row * SROW32 + f4 * 4) * 4u;
            cp_async16(dA, A + (size_t)gr * K_TOT + kc * 64 + f4 * 8);
            int gn = bn + row;
            uint32_t dB = sbase + (uint32_t)(buf * S_BUF32 + (128 + row) * SROW32 + f4 * 4) * 4u;
            cp_async16(dB, Bt + (size_t)gn * K_TOT + kc * 64 + f4 * 8);
        }
    };

    load_tile(0, 0);
    CP_COMMIT();

    for (int kc = 0; kc < NBK; kc++) {
        int buf = kc & 1;
        if (kc + 1 < NBK) {
            load_tile(kc + 1, buf ^ 1);
            CP_COMMIT();
            CP_WAIT(1);
        } else {
            CP_WAIT(0);
        }
        __syncthreads();

        const uint32_t* As = sm32 + buf * S_BUF32;
        const uint32_t* Bs = As + 128 * SROW32;
        const int rm = wm * 32;
        const int cn = wn * 64;

#pragma unroll
        for (int s = 0; s < 4; s++) {
            int k0u = s * 8;
            uint32_t af[2][4];
#pragma unroll
            for (int mi = 0; mi < 2; mi++) {
                int r0 = rm + mi * 16 + g;
                af[mi][0] = As[r0 * SROW32 + k0u + tig];
                af[mi][1] = As[(r0 + 8) * SROW32 + k0u + tig];
                af[mi][2] = As[r0 * SROW32 + k0u + 4 + tig];
                af[mi][3] = As[(r0 + 8) * SROW32 + k0u + 4 + tig];
            }
#pragma unroll
            for (int ni = 0; ni < 8; ni++) {
                int n0 = cn + ni * 8 + g;
                uint32_t bf[2];
                bf[0] = Bs[n0 * SROW32 + k0u + tig];
                bf[1] = Bs[n0 * SROW32 + k0u + 4 + tig];
                mma_f16(acc[0][ni], af[0], bf);
                mma_f16(acc[1][ni], af[1], bf);
            }
        }
        __syncthreads();
    }

#pragma unroll
    for (int mi = 0; mi < 2; mi++) {
#pragma unroll
        for (int h = 0; h < 2; h++) {
            int m = bm + wm * 32 + mi * 16 + g + h * 8;
            if (m >= M) continue;
#pragma unroll
            for (int ni = 0; ni < 8; ni++) {
                int n0 = bn + wn * 64 + ni * 8 + tig * 2;
                float v0 = acc[mi][ni][h * 2 + 0];
                float v1 = acc[mi][ni][h * 2 + 1];
                if (EPI == 0) {
                    *(__half2*)(C + (size_t)m * N_OUT + n0) = __floats2half2_rn(v0, v1);
                } else {
                    float r0v = fmaxf(v0 + bias[n0], 0.0f);
                    float r1v = fmaxf(v1 + bias[n0 + 1], 0.0f);
                    unsigned idx = (unsigned)m * (unsigned)N_OUT + (unsigned)n0;
                    unsigned w = mask[idx >> 5];
                    r0v = ((w >> (idx & 31)) & 1u) ? r0v * 2.0f : 0.0f;
                    r1v = ((w >> ((idx + 1) & 31)) & 1u) ? r1v * 2.0f : 0.0f;
                    *(__half2*)(C + (size_t)m * N_OUT + n0) = __floats2half2_rn(r0v, r1v);
                }
            }
        }
    }
}

// ---------------- aggregations ----------------------------------------------
__global__ void aggx_kernel(const float* __restrict__ x, int base) {
    int n = base + blockIdx.x, c = threadIdx.x;
    float dn = g_dinv[n];
    float acc = dn * x[(size_t)n * 256 + c];
    int k0 = g_off[n], k1 = g_off[n + 1];
    for (int k = k0; k < k1; k++) {
        int s = g_csr[k];
        acc += g_dinv[s] * x[(size_t)s * 256 + c];
    }
    g_aggx[(size_t)n * 256 + c] = __float2half(acc * dn);
}

// agg2: fp16 gather (half2), bias, relu, mask dropout -> out f32
__global__ void agg2_kernel(const __half* __restrict__ xw,
                            const float* __restrict__ bias,
                            float* __restrict__ out,
                            const unsigned* __restrict__ mask) {
    int n = blockIdx.x, c2 = threadIdx.x;   // 128 threads x 2 channels
    float dn = g_dinv[n];
    float2 hv = __half22float2(((const __half2*)(xw + (size_t)n * 256))[c2]);
    float a0 = dn * hv.x, a1 = dn * hv.y;
    int k0 = g_off[n], k1 = g_off[n + 1];
    for (int k = k0; k < k1; k++) {
        int s = g_csr[k];
        float ds = g_dinv[s];
        float2 sv = __half22float2(((const __half2*)(xw + (size_t)s * 256))[c2]);
        a0 += ds * sv.x;
        a1 += ds * sv.y;
    }
    int c = c2 * 2;
    float v0 = fmaxf(a0 * dn + bias[c], 0.0f);
    float v1 = fmaxf(a1 * dn + bias[c + 1], 0.0f);
    unsigned idx = (unsigned)(n * 256 + c);
    unsigned w = mask[idx >> 5];
    out[idx]     = ((w >> (idx & 31)) & 1u)       ? v0 * 2.0f : 0.0f;
    out[idx + 1] = ((w >> ((idx + 1) & 31)) & 1u) ? v1 * 2.0f : 0.0f;
}

// ---------------- launch -----------------------------------------------------
extern "C" void kernel_launch(void* const* d_in, const int* in_sizes, int n_in,
                              void* d_out, int out_size)
{
    const float* x  = (const float*)d_in[0];
    const void*  ei = d_in[1];
    const float* W1 = (const float*)d_in[2];
    const float* b1 = (const float*)d_in[3];
    const float* W2 = (const float*)d_in[4];
    const float* b2 = (const float*)d_in[5];
    float* out = (float*)d_out;

    __half *p_aggx, *p_h1, *p_xw2, *p_w1t, *p_w2t;
    unsigned *p_m1, *p_m2;
    cudaGetSymbolAddress((void**)&p_aggx, g_aggx);
    cudaGetSymbolAddress((void**)&p_h1,   g_h1);
    cudaGetSymbolAddress((void**)&p_xw2,  g_xw2);
    cudaGetSymbolAddress((void**)&p_w1t,  g_w1t);
    cudaGetSymbolAddress((void**)&p_w2t,  g_w2t);
    cudaGetSymbolAddress((void**)&p_m1,   g_mask1);
    cudaGetSymbolAddress((void**)&p_m2,   g_mask2);

    constexpr int SMEMB = 2 * S_BUF32 * 4;
    cudaFuncSetAttribute(hgemm_kernel<512, 256, 1>,
                         cudaFuncAttributeMaxDynamicSharedMemorySize, SMEMB);
    cudaFuncSetAttribute(hgemm_kernel<256, 512, 0>,
                         cudaFuncAttributeMaxDynamicSharedMemorySize, SMEMB);

    unsigned dk1_0, dk1_1, dk2_0, dk2_1;
    tf2x32(0u, 42u, 0u, 0u, dk1_0, dk1_1);
    tf2x32(0u, 42u, 0u, 1u, dk2_0, dk2_1);

    static cudaStream_t s1 = nullptr, s2 = nullptr;
    static cudaEvent_t ev_fork = nullptr, ev_join = nullptr, ev_fill = nullptr, ev_b1 = nullptr;
    if (s1 == nullptr) {
        cudaStreamCreateWithFlags(&s1, cudaStreamNonBlocking);
        cudaStreamCreateWithFlags(&s2, cudaStreamNonBlocking);
        cudaEventCreateWithFlags(&ev_fork, cudaEventDisableTiming);
        cudaEventCreateWithFlags(&ev_join, cudaEventDisableTiming);
        cudaEventCreateWithFlags(&ev_fill, cudaEventDisableTiming);
        cudaEventCreateWithFlags(&ev_b1,   cudaEventDisableTiming);
    }

    // side stream: transposes + both dropout masks
    cudaEventRecord(ev_fork, 0);
    cudaStreamWaitEvent(s2, ev_fork, 0);
    {
        dim3 blk(32, 8);
        transpose2_kernel<<<dim3(16, 16, 2), blk, 0, s2>>>(W1, W2);
        mask_kernel<<<20000, 256, 0, s2>>>(p_m1, dk1_0, dk1_1);
        mask_kernel<<<10000, 256, 0, s2>>>(p_m2, dk2_0, dk2_1);
    }
    cudaEventRecord(ev_join, s2);

    // main stream: preproc then chain A
    count_kernel<<<N_EDGES / 256, 256>>>(ei);
    scan_kernel<<<1, 1024>>>();
    fill_kernel<<<N_EDGES / 256, 256>>>(ei);
    cudaEventRecord(ev_fill, 0);

    aggx_kernel<<<SPLIT_M, 256>>>(x, 0);

    // chain B on s1 overlaps GEMM1A
    cudaStreamWaitEvent(s1, ev_fill, 0);
    aggx_kernel<<<N_NODES - SPLIT_M, 256, 0, s1>>>(x, SPLIT_M);
    cudaStreamWaitEvent(s1, ev_join, 0);
    hgemm_kernel<512, 256, 1><<<dim3(4, 39), 256, SMEMB, s1>>>(
        p_aggx, p_w1t, p_h1, b1, p_m1, N_NODES, SPLIT_M);
    cudaEventRecord(ev_b1, s1);

    cudaStreamWaitEvent(0, ev_join, 0);
    hgemm_kernel<512, 256, 1><<<dim3(4, 40), 256, SMEMB>>>(
        p_aggx, p_w1t, p_h1, b1, p_m1, N_NODES, 0);

    // layer 2
    cudaStreamWaitEvent(0, ev_b1, 0);
    hgemm_kernel<256, 512, 0><<<dim3(2, 79), 256, SMEMB>>>(
        p_h1, p_w2t, p_xw2, nullptr, nullptr, N_NODES, 0);
    agg2_kernel<<<N_NODES, 128>>>(p_xw2, b2, out, p_m2);
}

// round 9
// speedup vs baseline: 2.1499x; 1.1092x over previous
#include <cuda_runtime.h>
#include <cuda_fp16.h>
#include <stdint.h>

#define N_NODES 10000
#define N_EDGES 160000
#define M_PAD   10112           // 79 * 128
#define SPLIT_M 5120            // 40 tiles chain A, 39 chain B

// ---------------- device scratch (no allocations allowed) ----------------
__device__ __half g_xh  [N_NODES * 256];  // x, fp16
__device__ __half g_aggx[M_PAD * 256];    // ÂX, fp16
__device__ __half g_h1  [M_PAD * 512];    // layer-1 out, fp16
__device__ __half g_xw2 [N_NODES * 256];  // h1 @ W2, fp16
__device__ __half g_w1t [512 * 256];      // W1^T, fp16
__device__ __half g_w2t [256 * 512];      // W2^T, fp16
__device__ unsigned g_mask1[160000];      // 5.12M dropout bits (layer 1)
__device__ unsigned g_mask2[80000];       // 2.56M dropout bits (layer 2)
__device__ float g_dinv[N_NODES];
__device__ int   g_cnt[N_NODES];          // zero at load; scan self-clears
__device__ int   g_off[N_NODES + 1];
__device__ int   g_cur[N_NODES];
__device__ int   g_csr[N_EDGES];

// ---------------- PTX helpers ----------------
__device__ __forceinline__ uint32_t smem_to_u32(const void* p) {
    uint32_t a;
    asm("{ .reg .u64 t; cvta.to.shared.u64 t, %1; cvt.u32.u64 %0, t; }" : "=r"(a) : "l"(p));
    return a;
}
__device__ __forceinline__ void cp_async16(uint32_t dst, const void* src) {
    asm volatile("cp.async.cg.shared.global [%0], [%1], 16;" :: "r"(dst), "l"(src));
}
#define CP_COMMIT()  asm volatile("cp.async.commit_group;" ::: "memory")
#define CP_WAIT(n)   asm volatile("cp.async.wait_group %0;" :: "n"(n) : "memory")

__device__ __forceinline__ void mma_f16(float* d, const uint32_t* a, const uint32_t* b) {
    asm volatile(
        "mma.sync.aligned.m16n8k16.row.col.f32.f16.f16.f32 "
        "{%0,%1,%2,%3},{%4,%5,%6,%7},{%8,%9},{%0,%1,%2,%3};"
        : "+f"(d[0]), "+f"(d[1]), "+f"(d[2]), "+f"(d[3])
        : "r"(a[0]), "r"(a[1]), "r"(a[2]), "r"(a[3]), "r"(b[0]), "r"(b[1]));
}

// ---------------- threefry2x32 (JAX-compatible, validated) ----------------
#define TF_ROUND(v0, v1, r) do { (v0) += (v1); (v1) = ((v1) << (r)) | ((v1) >> (32 - (r))); (v1) ^= (v0); } while (0)
__host__ __device__ inline void tf2x32(unsigned k0, unsigned k1,
                                       unsigned x0, unsigned x1,
                                       unsigned& o0, unsigned& o1) {
    unsigned ks0 = k0, ks1 = k1, ks2 = k0 ^ k1 ^ 0x1BD11BDAu;
    unsigned v0 = x0 + ks0, v1 = x1 + ks1;
    TF_ROUND(v0, v1, 13); TF_ROUND(v0, v1, 15); TF_ROUND(v0, v1, 26); TF_ROUND(v0, v1, 6);
    v0 += ks1; v1 += ks2 + 1u;
    TF_ROUND(v0, v1, 17); TF_ROUND(v0, v1, 29); TF_ROUND(v0, v1, 16); TF_ROUND(v0, v1, 24);
    v0 += ks2; v1 += ks0 + 2u;
    TF_ROUND(v0, v1, 13); TF_ROUND(v0, v1, 15); TF_ROUND(v0, v1, 26); TF_ROUND(v0, v1, 6);
    v0 += ks0; v1 += ks1 + 3u;
    TF_ROUND(v0, v1, 17); TF_ROUND(v0, v1, 29); TF_ROUND(v0, v1, 16); TF_ROUND(v0, v1, 24);
    v0 += ks1; v1 += ks2 + 4u;
    TF_ROUND(v0, v1, 13); TF_ROUND(v0, v1, 15); TF_ROUND(v0, v1, 26); TF_ROUND(v0, v1, 6);
    v0 += ks2; v1 += ks0 + 5u;
    o0 = v0; o1 = v1;
}

// ---------------- preprocessing --------------------------------------------
// ILP-5 count: 125 blocks x 256 threads x 5 edges = exactly 160000.
__global__ void count_kernel(const void* __restrict__ ei) {
    int e0 = (blockIdx.x * blockDim.x + threadIdx.x) * 5;
    const unsigned* u = (const unsigned*)ei;
    unsigned hior = 0;
#pragma unroll
    for (int j = 0; j < 5; j++) hior |= u[2u * (unsigned)(e0 + j) + 1u];
    bool is64 = !__any_sync(0xffffffffu, hior != 0u);
    int d[5];
    if (is64) {
        const long long* p = (const long long*)ei + N_EDGES + e0;
#pragma unroll
        for (int j = 0; j < 5; j++) d[j] = (int)p[j];
    } else {
        const int* p = (const int*)ei + N_EDGES + e0;
#pragma unroll
        for (int j = 0; j < 5; j++) d[j] = p[j];
    }
#pragma unroll
    for (int j = 0; j < 5; j++) atomicAdd(&g_cnt[d[j]], 1);
}

// one-pass scan: 1024 threads x 10 elements, 3 barriers total
__global__ void scan_kernel() {
    __shared__ int warp_pre[32];
    const int t = threadIdx.x;
    const int lane = t & 31, wid = t >> 5;
    const int base = t * 10;
    int v[10];
    int sum = 0;
#pragma unroll
    for (int j = 0; j < 10; j++) {
        int i = base + j;
        int c = (i < N_NODES) ? g_cnt[i] : 0;
        v[j] = c;
        sum += c;
        if (i < N_NODES) {
            g_dinv[i] = rsqrtf((float)(c + 1));
            g_cnt[i] = 0;                       // self-clear for graph replay
        }
    }
    int incl = sum;
#pragma unroll
    for (int o = 1; o < 32; o <<= 1) {
        int x = __shfl_up_sync(0xffffffffu, incl, o);
        if (lane >= o) incl += x;
    }
    if (lane == 31) warp_pre[wid] = incl;
    __syncthreads();
    if (wid == 0) {
        int ws = warp_pre[lane];
        int wincl = ws;
#pragma unroll
        for (int o = 1; o < 32; o <<= 1) {
            int x = __shfl_up_sync(0xffffffffu, wincl, o);
            if (lane >= o) wincl += x;
        }
        warp_pre[lane] = wincl - ws;
    }
    __syncthreads();
    int excl = incl - sum + warp_pre[wid];
#pragma unroll
    for (int j = 0; j < 10; j++) {
        int i = base + j;
        if (i < N_NODES) {
            g_off[i] = excl;
            g_cur[i] = excl;
        }
        excl += v[j];
    }
    if (base + 10 >= N_NODES && base < N_NODES) g_off[N_NODES] = excl;
}

// ILP-5 fill (same exact-coverage grid as count)
__global__ void fill_kernel(const void* __restrict__ ei) {
    int e0 = (blockIdx.x * blockDim.x + threadIdx.x) * 5;
    const unsigned* u = (const unsigned*)ei;
    unsigned hior = 0;
#pragma unroll
    for (int j = 0; j < 5; j++) hior |= u[2u * (unsigned)(e0 + j) + 1u];
    bool is64 = !__any_sync(0xffffffffu, hior != 0u);
    int s[5], d[5];
    if (is64) {
        const long long* ps = (const long long*)ei + e0;
        const long long* pd = (const long long*)ei + N_EDGES + e0;
#pragma unroll
        for (int j = 0; j < 5; j++) { s[j] = (int)ps[j]; d[j] = (int)pd[j]; }
    } else {
        const int* ps = (const int*)ei + e0;
        const int* pd = (const int*)ei + N_EDGES + e0;
#pragma unroll
        for (int j = 0; j < 5; j++) { s[j] = ps[j]; d[j] = pd[j]; }
    }
#pragma unroll
    for (int j = 0; j < 5; j++)
        g_csr[atomicAdd(&g_cur[d[j]], 1)] = s[j];
}

// x -> fp16 (vectorized)
__global__ void xh_kernel(const float* __restrict__ x) {
    int i = blockIdx.x * blockDim.x + threadIdx.x;   // float4 index
    float4 v = ((const float4*)x)[i];
    __half2 h0 = __floats2half2_rn(v.x, v.y);
    __half2 h1 = __floats2half2_rn(v.z, v.w);
    ((uint2*)g_xh)[i] = make_uint2(*(uint32_t*)&h0, *(uint32_t*)&h1);
}

// two transposes -> fp16
__global__ void transpose2_kernel(const float* __restrict__ W1,
                                  const float* __restrict__ W2) {
    __shared__ float tile[32][33];
    int z = blockIdx.z;
    const float* src = (z == 0) ? W1 : W2;
    __half* dst = (z == 0) ? g_w1t : g_w2t;
    int R = (z == 0) ? 256 : 512;
    int C = (z == 0) ? 512 : 256;
    if (blockIdx.x * 32 >= C || blockIdx.y * 32 >= R) return;
    int c0 = blockIdx.x * 32, r0 = blockIdx.y * 32;
#pragma unroll
    for (int i = 0; i < 32; i += 8) {
        int r = r0 + threadIdx.y + i, c = c0 + threadIdx.x;
        tile[threadIdx.y + i][threadIdx.x] = src[(size_t)r * C + c];
    }
    __syncthreads();
#pragma unroll
    for (int i = 0; i < 32; i += 8) {
        int c = c0 + threadIdx.y + i, r = r0 + threadIdx.x;
        dst[(size_t)c * R + r] = __float2half(tile[threadIdx.x][threadIdx.y + i]);
    }
}

// dropout bitmask
__global__ void mask_kernel(unsigned* __restrict__ mask, unsigned k0, unsigned k1) {
    unsigned i = blockIdx.x * 256u + threadIdx.x;
    unsigned y0, y1;
    tf2x32(k0, k1, 0u, i, y0, y1);
    unsigned bits = y0 ^ y1;
    float u = __uint_as_float((bits >> 9) | 0x3f800000u) - 1.0f;
    unsigned ball = __ballot_sync(0xffffffffu, u < 0.5f);
    if ((threadIdx.x & 31) == 0) mask[i >> 5] = ball;
}

// ---------------- fp16 tensor-core GEMM -------------------------------------
#define SROW32 36
#define S_BUF32 (256 * SROW32)

template <int N_OUT, int K_TOT, int EPI>
__global__ void __launch_bounds__(256, 2)
hgemm_kernel(const __half* __restrict__ A, const __half* __restrict__ Bt,
             __half* __restrict__ C, const float* __restrict__ bias,
             const unsigned* __restrict__ mask, int M, int m0)
{
    extern __shared__ uint32_t sm32[];
    const int tid = threadIdx.x;
    const int wid = tid >> 5, lane = tid & 31;
    const int g = lane >> 2, tig = lane & 3;
    const int wm = wid >> 1, wn = wid & 1;
    const int bm = m0 + blockIdx.y * 128;
    const int bn = blockIdx.x * 128;
    constexpr int NBK = K_TOT / 64;

    const uint32_t sbase = smem_to_u32(sm32);

    float acc[2][8][4];
#pragma unroll
    for (int mi = 0; mi < 2; mi++)
#pragma unroll
        for (int ni = 0; ni < 8; ni++)
#pragma unroll
            for (int j = 0; j < 4; j++) acc[mi][ni][j] = 0.0f;

    auto load_tile = [&](int kc, int buf) {
#pragma unroll
        for (int r = 0; r < 4; r++) {
            int chunk = r * 256 + tid;
            int row = chunk >> 3;
            int f4  = chunk & 7;
            int gr = bm + row; if (gr >= M) gr = M - 1;
            uint32_t dA = sbase + (uint32_t)(buf * S_BUF32 + row * SROW32 + f4 * 4) * 4u;
            cp_async16(dA, A + (size_t)gr * K_TOT + kc * 64 + f4 * 8);
            int gn = bn + row;
            uint32_t dB = sbase + (uint32_t)(buf * S_BUF32 + (128 + row) * SROW32 + f4 * 4) * 4u;
            cp_async16(dB, Bt + (size_t)gn * K_TOT + kc * 64 + f4 * 8);
        }
    };

    load_tile(0, 0);
    CP_COMMIT();

    for (int kc = 0; kc < NBK; kc++) {
        int buf = kc & 1;
        if (kc + 1 < NBK) {
            load_tile(kc + 1, buf ^ 1);
            CP_COMMIT();
            CP_WAIT(1);
        } else {
            CP_WAIT(0);
        }
        __syncthreads();

        const uint32_t* As = sm32 + buf * S_BUF32;
        const uint32_t* Bs = As + 128 * SROW32;
        const int rm = wm * 32;
        const int cn = wn * 64;

#pragma unroll
        for (int s = 0; s < 4; s++) {
            int k0u = s * 8;
            uint32_t af[2][4];
#pragma unroll
            for (int mi = 0; mi < 2; mi++) {
                int r0 = rm + mi * 16 + g;
                af[mi][0] = As[r0 * SROW32 + k0u + tig];
                af[mi][1] = As[(r0 + 8) * SROW32 + k0u + tig];
                af[mi][2] = As[r0 * SROW32 + k0u + 4 + tig];
                af[mi][3] = As[(r0 + 8) * SROW32 + k0u + 4 + tig];
            }
#pragma unroll
            for (int ni = 0; ni < 8; ni++) {
                int n0 = cn + ni * 8 + g;
                uint32_t bf[2];
                bf[0] = Bs[n0 * SROW32 + k0u + tig];
                bf[1] = Bs[n0 * SROW32 + k0u + 4 + tig];
                mma_f16(acc[0][ni], af[0], bf);
                mma_f16(acc[1][ni], af[1], bf);
            }
        }
        __syncthreads();
    }

#pragma unroll
    for (int mi = 0; mi < 2; mi++) {
#pragma unroll
        for (int h = 0; h < 2; h++) {
            int m = bm + wm * 32 + mi * 16 + g + h * 8;
            if (m >= M) continue;
#pragma unroll
            for (int ni = 0; ni < 8; ni++) {
                int n0 = bn + wn * 64 + ni * 8 + tig * 2;
                float v0 = acc[mi][ni][h * 2 + 0];
                float v1 = acc[mi][ni][h * 2 + 1];
                if (EPI == 0) {
                    *(__half2*)(C + (size_t)m * N_OUT + n0) = __floats2half2_rn(v0, v1);
                } else {
                    float r0v = fmaxf(v0 + bias[n0], 0.0f);
                    float r1v = fmaxf(v1 + bias[n0 + 1], 0.0f);
                    unsigned idx = (unsigned)m * (unsigned)N_OUT + (unsigned)n0;
                    unsigned w = mask[idx >> 5];
                    r0v = ((w >> (idx & 31)) & 1u) ? r0v * 2.0f : 0.0f;
                    r1v = ((w >> ((idx + 1) & 31)) & 1u) ? r1v * 2.0f : 0.0f;
                    *(__half2*)(C + (size_t)m * N_OUT + n0) = __floats2half2_rn(r0v, r1v);
                }
            }
        }
    }
}

// ---------------- aggregations (half2 gathers) -------------------------------
__global__ void aggx_kernel(int base) {
    int n = base + blockIdx.x, c2 = threadIdx.x;   // 128 threads x 2 channels
    float dn = g_dinv[n];
    float2 hv = __half22float2(((const __half2*)(g_xh + (size_t)n * 256))[c2]);
    float a0 = dn * hv.x, a1 = dn * hv.y;
    int k0 = g_off[n], k1 = g_off[n + 1];
    for (int k = k0; k < k1; k++) {
        int s = g_csr[k];
        float ds = g_dinv[s];
        float2 sv = __half22float2(((const __half2*)(g_xh + (size_t)s * 256))[c2]);
        a0 += ds * sv.x;
        a1 += ds * sv.y;
    }
    ((__half2*)(g_aggx + (size_t)n * 256))[c2] = __floats2half2_rn(a0 * dn, a1 * dn);
}

__global__ void agg2_kernel(const __half* __restrict__ xw,
                            const float* __restrict__ bias,
                            float* __restrict__ out,
                            const unsigned* __restrict__ mask) {
    int n = blockIdx.x, c2 = threadIdx.x;
    float dn = g_dinv[n];
    float2 hv = __half22float2(((const __half2*)(xw + (size_t)n * 256))[c2]);
    float a0 = dn * hv.x, a1 = dn * hv.y;
    int k0 = g_off[n], k1 = g_off[n + 1];
    for (int k = k0; k < k1; k++) {
        int s = g_csr[k];
        float ds = g_dinv[s];
        float2 sv = __half22float2(((const __half2*)(xw + (size_t)s * 256))[c2]);
        a0 += ds * sv.x;
        a1 += ds * sv.y;
    }
    int c = c2 * 2;
    float v0 = fmaxf(a0 * dn + bias[c], 0.0f);
    float v1 = fmaxf(a1 * dn + bias[c + 1], 0.0f);
    unsigned idx = (unsigned)(n * 256 + c);
    unsigned w = mask[idx >> 5];
    out[idx]     = ((w >> (idx & 31)) & 1u)       ? v0 * 2.0f : 0.0f;
    out[idx + 1] = ((w >> ((idx + 1) & 31)) & 1u) ? v1 * 2.0f : 0.0f;
}

// ---------------- launch -----------------------------------------------------
extern "C" void kernel_launch(void* const* d_in, const int* in_sizes, int n_in,
                              void* d_out, int out_size)
{
    const float* x  = (const float*)d_in[0];
    const void*  ei = d_in[1];
    const float* W1 = (const float*)d_in[2];
    const float* b1 = (const float*)d_in[3];
    const float* W2 = (const float*)d_in[4];
    const float* b2 = (const float*)d_in[5];
    float* out = (float*)d_out;

    __half *p_aggx, *p_h1, *p_xw2, *p_w1t, *p_w2t;
    unsigned *p_m1, *p_m2;
    cudaGetSymbolAddress((void**)&p_aggx, g_aggx);
    cudaGetSymbolAddress((void**)&p_h1,   g_h1);
    cudaGetSymbolAddress((void**)&p_xw2,  g_xw2);
    cudaGetSymbolAddress((void**)&p_w1t,  g_w1t);
    cudaGetSymbolAddress((void**)&p_w2t,  g_w2t);
    cudaGetSymbolAddress((void**)&p_m1,   g_mask1);
    cudaGetSymbolAddress((void**)&p_m2,   g_mask2);

    constexpr int SMEMB = 2 * S_BUF32 * 4;
    cudaFuncSetAttribute(hgemm_kernel<512, 256, 1>,
                         cudaFuncAttributeMaxDynamicSharedMemorySize, SMEMB);
    cudaFuncSetAttribute(hgemm_kernel<256, 512, 0>,
                         cudaFuncAttributeMaxDynamicSharedMemorySize, SMEMB);

    unsigned dk1_0, dk1_1, dk2_0, dk2_1;
    tf2x32(0u, 42u, 0u, 0u, dk1_0, dk1_1);
    tf2x32(0u, 42u, 0u, 1u, dk2_0, dk2_1);

    static cudaStream_t s1 = nullptr, s2 = nullptr;
    static cudaEvent_t ev_fork = nullptr, ev_join = nullptr, ev_fill = nullptr,
                       ev_b1 = nullptr, ev_xh = nullptr;
    if (s1 == nullptr) {
        cudaStreamCreateWithFlags(&s1, cudaStreamNonBlocking);
        cudaStreamCreateWithFlags(&s2, cudaStreamNonBlocking);
        cudaEventCreateWithFlags(&ev_fork, cudaEventDisableTiming);
        cudaEventCreateWithFlags(&ev_join, cudaEventDisableTiming);
        cudaEventCreateWithFlags(&ev_fill, cudaEventDisableTiming);
        cudaEventCreateWithFlags(&ev_b1,   cudaEventDisableTiming);
        cudaEventCreateWithFlags(&ev_xh,   cudaEventDisableTiming);
    }

    // side stream: xh conversion first (aggx needs it), then weights + masks
    cudaEventRecord(ev_fork, 0);
    cudaStreamWaitEvent(s2, ev_fork, 0);
    {
        xh_kernel<<<(N_NODES * 256 / 4) / 256, 256, 0, s2>>>(x);
        cudaEventRecord(ev_xh, s2);
        dim3 blk(32, 8);
        transpose2_kernel<<<dim3(16, 16, 2), blk, 0, s2>>>(W1, W2);
        mask_kernel<<<20000, 256, 0, s2>>>(p_m1, dk1_0, dk1_1);
        mask_kernel<<<10000, 256, 0, s2>>>(p_m2, dk2_0, dk2_1);
    }
    cudaEventRecord(ev_join, s2);

    // main stream: preproc (exact-coverage ILP-5 grids: 125 x 256 x 5 = 160000)
    count_kernel<<<125, 256>>>(ei);
    scan_kernel<<<1, 1024>>>();
    fill_kernel<<<125, 256>>>(ei);
    cudaEventRecord(ev_fill, 0);

    cudaStreamWaitEvent(0, ev_xh, 0);
    aggx_kernel<<<SPLIT_M, 128>>>(0);

    // chain B on s1 overlaps GEMM1A
    cudaStreamWaitEvent(s1, ev_fill, 0);
    cudaStreamWaitEvent(s1, ev_xh, 0);
    aggx_kernel<<<N_NODES - SPLIT_M, 128, 0, s1>>>(SPLIT_M);
    cudaStreamWaitEvent(s1, ev_join, 0);
    hgemm_kernel<512, 256, 1><<<dim3(4, 39), 256, SMEMB, s1>>>(
        p_aggx, p_w1t, p_h1, b1, p_m1, N_NODES, SPLIT_M);
    cudaEventRecord(ev_b1, s1);

    cudaStreamWaitEvent(0, ev_join, 0);
    hgemm_kernel<512, 256, 1><<<dim3(4, 40), 256, SMEMB>>>(
        p_aggx, p_w1t, p_h1, b1, p_m1, N_NODES, 0);

    // layer 2
    cudaStreamWaitEvent(0, ev_b1, 0);
    hgemm_kernel<256, 512, 0><<<dim3(2, 79), 256, SMEMB>>>(
        p_h1, p_w2t, p_xw2, nullptr, nullptr, N_NODES, 0);
    agg2_kernel<<<N_NODES, 128>>>(p_xw2, b2, out, p_m2);
}